// round 5
// baseline (speedup 1.0000x reference)
#include <cuda_runtime.h>
#include <cuda_bf16.h>
#include <math.h>
#include <stdint.h>

// ---------------------------------------------------------------------------
// Problem constants
// ---------------------------------------------------------------------------
#define L     4096
#define HID   2560
#define NH    8
#define NKV   4
#define HD    256
#define QD    (NH*HD)    // 2048
#define KD    (NKV*HD)   // 1024
#define SCALING 0.0625f
#define SEQ   1024

// ---------------------------------------------------------------------------
// Scratch
// ---------------------------------------------------------------------------
__device__ float g_Q[L * QD];
__device__ float g_K[L * KD];
__device__ float g_V[L * KD];
__device__ float g_A[L * QD];
// tf32 hi/lo splits for attention
__device__ float g_Qh[L * QD];
__device__ float g_Ql[L * QD];
__device__ float g_Kh[L * KD];
__device__ float g_Kl[L * KD];
__device__ float g_Vh[L * KD];
__device__ float g_Vl[L * KD];
// bf16 hi/lo operands for GEMMs
__device__ __nv_bfloat16 g_hsh[L * HID], g_hsl[L * HID];
__device__ __nv_bfloat16 g_Wqth[QD * HID], g_Wqtl[QD * HID];   // [N][K]
__device__ __nv_bfloat16 g_Wkth[KD * HID], g_Wktl[KD * HID];
__device__ __nv_bfloat16 g_Wvth[KD * HID], g_Wvtl[KD * HID];
__device__ __nv_bfloat16 g_Woth[HID * QD], g_Wotl[HID * QD];
__device__ __nv_bfloat16 g_Abh[L * QD], g_Abl[L * QD];

// ---------------------------------------------------------------------------
// helpers
// ---------------------------------------------------------------------------
__device__ __forceinline__ uint32_t tf32r(float x) {
    uint32_t u;
    asm("cvt.rna.tf32.f32 %0, %1;" : "=r"(u) : "f"(x));
    return u;
}
__device__ __forceinline__ void split_tf32(float x, float& hi, float& lo) {
    uint32_t h = tf32r(x);
    hi = __uint_as_float(h);
    lo = __uint_as_float(tf32r(x - hi));
}
__device__ __forceinline__ void mma8(float* c, const uint32_t* a, const uint32_t* b) {
    asm volatile(
        "mma.sync.aligned.m16n8k8.row.col.f32.tf32.tf32.f32 "
        "{%0,%1,%2,%3}, {%4,%5,%6,%7}, {%8,%9}, {%0,%1,%2,%3};"
        : "+f"(c[0]), "+f"(c[1]), "+f"(c[2]), "+f"(c[3])
        : "r"(a[0]), "r"(a[1]), "r"(a[2]), "r"(a[3]), "r"(b[0]), "r"(b[1]));
}
__device__ __forceinline__ void mma16bf(float* c, const uint32_t* a, const uint32_t* b) {
    asm volatile(
        "mma.sync.aligned.m16n8k16.row.col.f32.bf16.bf16.f32 "
        "{%0,%1,%2,%3}, {%4,%5,%6,%7}, {%8,%9}, {%0,%1,%2,%3};"
        : "+f"(c[0]), "+f"(c[1]), "+f"(c[2]), "+f"(c[3])
        : "r"(a[0]), "r"(a[1]), "r"(a[2]), "r"(a[3]), "r"(b[0]), "r"(b[1]));
}
__device__ __forceinline__ void ldsm4(uint32_t* r, uint32_t addr) {
    asm volatile("ldmatrix.sync.aligned.m8n8.x4.shared.b16 {%0,%1,%2,%3}, [%4];"
                 : "=r"(r[0]), "=r"(r[1]), "=r"(r[2]), "=r"(r[3]) : "r"(addr));
}
__device__ __forceinline__ void cpasync16(uint32_t s, const void* g) {
    asm volatile("cp.async.cg.shared.global [%0], [%1], 16;" :: "r"(s), "l"(g));
}

// ---------------------------------------------------------------------------
// prep kernels
// ---------------------------------------------------------------------------
__global__ void split_bf16_kernel(const float* __restrict__ in,
                                  __nv_bfloat16* __restrict__ oh,
                                  __nv_bfloat16* __restrict__ ol, int n4)
{
    int i = blockIdx.x * blockDim.x + threadIdx.x;
    if (i >= n4) return;
    float4 v = ((const float4*)in)[i];
    __nv_bfloat16 h0 = __float2bfloat16(v.x);
    __nv_bfloat16 h1 = __float2bfloat16(v.y);
    __nv_bfloat16 h2 = __float2bfloat16(v.z);
    __nv_bfloat16 h3 = __float2bfloat16(v.w);
    __nv_bfloat16 l0 = __float2bfloat16(v.x - __bfloat162float(h0));
    __nv_bfloat16 l1 = __float2bfloat16(v.y - __bfloat162float(h1));
    __nv_bfloat16 l2 = __float2bfloat16(v.z - __bfloat162float(h2));
    __nv_bfloat16 l3 = __float2bfloat16(v.w - __bfloat162float(h3));
    ((__nv_bfloat162*)oh)[2 * i]     = __nv_bfloat162(h0, h1);
    ((__nv_bfloat162*)oh)[2 * i + 1] = __nv_bfloat162(h2, h3);
    ((__nv_bfloat162*)ol)[2 * i]     = __nv_bfloat162(l0, l1);
    ((__nv_bfloat162*)ol)[2 * i + 1] = __nv_bfloat162(l2, l3);
}

// W[K][N] f32 -> Th/Tl[N][K] bf16
__global__ void transpose_split_kernel(const float* __restrict__ W,
                                       __nv_bfloat16* __restrict__ Th,
                                       __nv_bfloat16* __restrict__ Tl,
                                       int Kdim, int Ndim)
{
    __shared__ float t[32][33];
    const int k0 = blockIdx.y * 32, n0 = blockIdx.x * 32;
    const int tx = threadIdx.x, ty = threadIdx.y;
#pragma unroll
    for (int j = 0; j < 4; j++)
        t[ty + j * 8][tx] = W[(size_t)(k0 + ty + j * 8) * Ndim + n0 + tx];
    __syncthreads();
#pragma unroll
    for (int j = 0; j < 4; j++) {
        float x = t[tx][ty + j * 8];
        __nv_bfloat16 h = __float2bfloat16(x);
        __nv_bfloat16 l = __float2bfloat16(x - __bfloat162float(h));
        size_t off = (size_t)(n0 + ty + j * 8) * Kdim + k0 + tx;
        Th[off] = h;
        Tl[off] = l;
    }
}

__global__ void split_tf32_kernel(const float* __restrict__ in,
                                  float* __restrict__ oh,
                                  float* __restrict__ ol, int n4)
{
    int i = blockIdx.x * blockDim.x + threadIdx.x;
    if (i >= n4) return;
    float4 v = ((const float4*)in)[i];
    float4 h, l;
    split_tf32(v.x, h.x, l.x);
    split_tf32(v.y, h.y, l.y);
    split_tf32(v.z, h.z, l.z);
    split_tf32(v.w, h.w, l.w);
    ((float4*)oh)[i] = h;
    ((float4*)ol)[i] = l;
}

// ---------------------------------------------------------------------------
// bf16-split GEMM: C[M,Ntot](f32) = A @ B^T
//   A: [M][K] hi/lo bf16 row-major; B: [Ntot][K] hi/lo bf16 (pre-transposed).
//   D = Ah*Bh + Ah*Bl + Al*Bh, fp32 accumulators.
// 128x128 tile / 256 thr / 8 warps (2x4), warp tile 64x32, K-chunk 32.
// mma.m16n8k16.bf16 + ldmatrix.x4, cp.async double buffered.
// ---------------------------------------------------------------------------
#define SAB 40                     // bf16 row stride (80B, ldmatrix conflict-free)
#define TILE_E (128*SAB)           // 5120 elems / tile
#define STG_E (4*TILE_E)           // Ah,Al,Bh,Bl
#define BGSM (2*STG_E*2)           // bytes (81920)

__global__ __launch_bounds__(256)
void bf16gemm(const __nv_bfloat16* __restrict__ Ahp, const __nv_bfloat16* __restrict__ Alp,
              const __nv_bfloat16* __restrict__ Bhp, const __nv_bfloat16* __restrict__ Blp,
              float* __restrict__ C, int Ntot, int K)
{
    extern __shared__ __nv_bfloat16 sb16[];
    const int tid  = threadIdx.x;
    const int lane = tid & 31, wid = tid >> 5;
    const int wm = wid >> 2, wn = wid & 3;
    const int g = lane >> 2, t = lane & 3;
    const int m0 = blockIdx.y * 128, n0 = blockIdx.x * 128;

    const uint32_t sbase = (uint32_t)__cvta_generic_to_shared(sb16);

    const __nv_bfloat16* base0 = Ahp + (size_t)m0 * K;
    const __nv_bfloat16* base1 = Alp + (size_t)m0 * K;
    const __nv_bfloat16* base2 = Bhp + (size_t)n0 * K;
    const __nv_bfloat16* base3 = Blp + (size_t)n0 * K;

    float acc[4][4][4];
#pragma unroll
    for (int mt = 0; mt < 4; mt++)
#pragma unroll
        for (int nt = 0; nt < 4; nt++)
#pragma unroll
            for (int r = 0; r < 4; r++) acc[mt][nt][r] = 0.f;

    // ldmatrix lane offsets (elems)
    // A matrices: (m0,k0),(m8,k0),(m0,k8),(m8,k8)
    const int a_off = ((lane & 7) + ((lane >> 3) & 1) * 8) * SAB + ((lane >> 4) & 1) * 8;
    // B matrices: (n0,k0),(n0,k8),(n8,k0),(n8,k8)
    const int b_off = ((lane & 7) + ((lane >> 4) & 1) * 8) * SAB + ((lane >> 3) & 1) * 8;

    auto issue_copy = [&](int c, int buf) {
        const int koff = c * 32;
#pragma unroll
        for (int i = 0; i < 8; i++) {
            const int f = tid + i * 256;
            const int tile = f >> 9;
            const int slot = f & 511;
            const int row = slot >> 2, seg = slot & 3;
            const __nv_bfloat16* gp;
            if      (tile == 0) gp = base0 + (size_t)row * K + koff + seg * 8;
            else if (tile == 1) gp = base1 + (size_t)row * K + koff + seg * 8;
            else if (tile == 2) gp = base2 + (size_t)row * K + koff + seg * 8;
            else                gp = base3 + (size_t)row * K + koff + seg * 8;
            const uint32_t dst = sbase +
                (uint32_t)(buf * STG_E + tile * TILE_E + row * SAB + seg * 8) * 2;
            cpasync16(dst, gp);
        }
        asm volatile("cp.async.commit_group;" ::: "memory");
    };

    const int nkb = K >> 5;
    issue_copy(0, 0);

    for (int kb = 0; kb < nkb; kb++) {
        const int cur = kb & 1;
        if (kb + 1 < nkb) {
            issue_copy(kb + 1, cur ^ 1);
            asm volatile("cp.async.wait_group 1;" ::: "memory");
        } else {
            asm volatile("cp.async.wait_group 0;" ::: "memory");
        }
        __syncthreads();

        const uint32_t stg = sbase + (uint32_t)(cur * STG_E) * 2;
        const uint32_t sAh = stg;
        const uint32_t sAl = stg + (uint32_t)TILE_E * 2;
        const uint32_t sBh = stg + (uint32_t)(2 * TILE_E) * 2;
        const uint32_t sBl = stg + (uint32_t)(3 * TILE_E) * 2;

#pragma unroll
        for (int ks = 0; ks < 2; ks++) {
            const int kbase = ks * 16;
            uint32_t ah[4][4], al[4][4], bh[2][4], bl[2][4];
#pragma unroll
            for (int mt = 0; mt < 4; mt++) {
                const uint32_t ao =
                    (uint32_t)((wm * 64 + mt * 16) * SAB + kbase + a_off) * 2;
                ldsm4(ah[mt], sAh + ao);
                ldsm4(al[mt], sAl + ao);
            }
#pragma unroll
            for (int np = 0; np < 2; np++) {
                const uint32_t bo =
                    (uint32_t)((wn * 32 + np * 16) * SAB + kbase + b_off) * 2;
                ldsm4(bh[np], sBh + bo);
                ldsm4(bl[np], sBl + bo);
            }
#pragma unroll
            for (int mt = 0; mt < 4; mt++)
#pragma unroll
                for (int nt = 0; nt < 4; nt++) {
                    const int pr = nt >> 1, hf = (nt & 1) * 2;
                    uint32_t bH[2] = { bh[pr][hf], bh[pr][hf + 1] };
                    uint32_t bL[2] = { bl[pr][hf], bl[pr][hf + 1] };
                    mma16bf(acc[mt][nt], ah[mt], bH);
                    mma16bf(acc[mt][nt], ah[mt], bL);
                    mma16bf(acc[mt][nt], al[mt], bH);
                }
        }
        __syncthreads();
    }

    // epilogue
#pragma unroll
    for (int mt = 0; mt < 4; mt++) {
        const int r0 = m0 + wm * 64 + mt * 16 + g;
#pragma unroll
        for (int nt = 0; nt < 4; nt++) {
            const int c0 = n0 + wn * 32 + nt * 8 + t * 2;
            *(float2*)&C[(size_t)r0 * Ntot + c0] =
                make_float2(acc[mt][nt][0], acc[mt][nt][1]);
            *(float2*)&C[(size_t)(r0 + 8) * Ntot + c0] =
                make_float2(acc[mt][nt][2], acc[mt][nt][3]);
        }
    }
}

// ---------------------------------------------------------------------------
// RMSNorm + RoPE with tf32 hi/lo split output
// ---------------------------------------------------------------------------
__global__ __launch_bounds__(256)
void norm_rope_split_kernel(const float* __restrict__ X, int hstride,
                            const float* __restrict__ w,
                            const float* __restrict__ cosp,
                            const float* __restrict__ sinp,
                            float* __restrict__ Xh, float* __restrict__ Xl)
{
    const int t = blockIdx.x;
    const int h = blockIdx.y;
    const int d = threadIdx.x;

    const size_t off = (size_t)t * hstride + h * HD + d;
    float x = X[off];

    float v = x * x;
#pragma unroll
    for (int o = 16; o; o >>= 1) v += __shfl_xor_sync(0xffffffffu, v, o);

    __shared__ float ws[8];
    __shared__ float buf[HD];
    if ((d & 31) == 0) ws[d >> 5] = v;
    __syncthreads();
    float ss = ws[0] + ws[1] + ws[2] + ws[3] + ws[4] + ws[5] + ws[6] + ws[7];

    float r = rsqrtf(ss * (1.0f / HD) + 1e-6f);
    float xn = x * r * (1.0f + w[d]);
    buf[d] = xn;
    __syncthreads();

    float rot = (d < HD / 2) ? -buf[d + HD / 2] : buf[d - HD / 2];
    float c = cosp[(size_t)t * HD + d];
    float s = sinp[(size_t)t * HD + d];
    float xr = xn * c + rot * s;

    float hi, lo;
    split_tf32(xr, hi, lo);
    Xh[off] = hi;
    Xl[off] = lo;
}

// ---------------------------------------------------------------------------
// Flash attention on tensor cores (3xTF32) — round-3 proven version
// ---------------------------------------------------------------------------
#define SQ 260
#define SC 68
#define OQH 0
#define OQL (OQH + 64*SQ)
#define OKH (OQL + 64*SQ)
#define OKL (OKH + 64*SC)
#define OPH (OKL + 64*SC)
#define OPL (OPH + 64*SC)
#define OPM (OPL + 64*SC)
#define OPS (OPM + 128)
#define ATT_SMEM ((OPS + 128) * 4)

__global__ __launch_bounds__(256, 1)
void attn_mma_kernel()
{
    extern __shared__ float sm[];
    float* Qh = sm + OQH;
    float* Ql = sm + OQL;
    float* Kh = sm + OKH;
    float* Kl = sm + OKL;
    float* Ph = sm + OPH;
    float* Pl = sm + OPL;
    float* pm = sm + OPM;
    float* ps = sm + OPS;

    const int qt  = blockIdx.x;
    const int seq = blockIdx.y;
    const int h   = blockIdx.z;
    const int kvh = h >> 1;

    const int tid  = threadIdx.x;
    const int lane = tid & 31, wid = tid >> 5;
    const int wm = wid >> 1, wn = wid & 1;
    const int g = lane >> 2, t = lane & 3;

    const int t0 = seq * SEQ + qt * 64;
    const uint32_t sb = (uint32_t)__cvta_generic_to_shared(sm);

    {
        const float* gqh = g_Qh + (size_t)t0 * QD + h * HD;
        const float* gql = g_Ql + (size_t)t0 * QD + h * HD;
#pragma unroll
        for (int i = 0; i < 16; i++) {
            int f = tid + i * 256;
            int row = f >> 6, c4 = (f & 63) * 4;
            cpasync16(sb + (uint32_t)(OQH + row * SQ + c4) * 4, gqh + (size_t)row * QD + c4);
            cpasync16(sb + (uint32_t)(OQL + row * SQ + c4) * 4, gql + (size_t)row * QD + c4);
        }
        asm volatile("cp.async.commit_group;" ::: "memory");
        asm volatile("cp.async.wait_group 0;" ::: "memory");
    }
    __syncthreads();

    float O[4][4][4];
#pragma unroll
    for (int dc = 0; dc < 4; dc++)
#pragma unroll
        for (int nt = 0; nt < 4; nt++)
#pragma unroll
            for (int r = 0; r < 4; r++) O[dc][nt][r] = 0.f;
    float m0 = -INFINITY, m1 = -INFINITY, l0 = 0.f, l1 = 0.f;

    for (int kt = 0; kt <= qt; kt++) {
        const int k0 = seq * SEQ + kt * 64;

        float S[4][4];
#pragma unroll
        for (int nt = 0; nt < 4; nt++)
#pragma unroll
            for (int r = 0; r < 4; r++) S[nt][r] = 0.f;

        for (int dc = 0; dc < 4; dc++) {
            __syncthreads();
#pragma unroll
            for (int i = 0; i < 4; i++) {
                int f = tid + i * 256;
                int row = f >> 4, c4 = (f & 15) * 4;
                size_t src = (size_t)(k0 + row) * KD + kvh * HD + dc * 64 + c4;
                cpasync16(sb + (uint32_t)(OKH + row * SC + c4) * 4, g_Kh + src);
                cpasync16(sb + (uint32_t)(OKL + row * SC + c4) * 4, g_Kl + src);
            }
            asm volatile("cp.async.commit_group;" ::: "memory");
            asm volatile("cp.async.wait_group 0;" ::: "memory");
            __syncthreads();

#pragma unroll
            for (int ks = 0; ks < 8; ks++) {
                uint32_t ah[4], al[4];
                const int ab = (wm * 16 + g) * SQ + dc * 64 + ks * 8 + t;
                ah[0] = __float_as_uint(Qh[ab]);
                ah[1] = __float_as_uint(Qh[ab + 8 * SQ]);
                ah[2] = __float_as_uint(Qh[ab + 4]);
                ah[3] = __float_as_uint(Qh[ab + 8 * SQ + 4]);
                al[0] = __float_as_uint(Ql[ab]);
                al[1] = __float_as_uint(Ql[ab + 8 * SQ]);
                al[2] = __float_as_uint(Ql[ab + 4]);
                al[3] = __float_as_uint(Ql[ab + 8 * SQ + 4]);
#pragma unroll
                for (int nt = 0; nt < 4; nt++) {
                    const int kb = (wn * 32 + nt * 8 + g) * SC + ks * 8 + t;
                    uint32_t bh[2], bl[2];
                    bh[0] = __float_as_uint(Kh[kb]);
                    bh[1] = __float_as_uint(Kh[kb + 4]);
                    bl[0] = __float_as_uint(Kl[kb]);
                    bl[1] = __float_as_uint(Kl[kb + 4]);
                    mma8(S[nt], ah, bh);
                    mma8(S[nt], ah, bl);
                    mma8(S[nt], al, bh);
                }
            }
        }

#pragma unroll
        for (int nt = 0; nt < 4; nt++) {
#pragma unroll
            for (int r = 0; r < 4; r++) S[nt][r] *= SCALING;
            if (kt == qt) {
                const int cl = wn * 32 + nt * 8 + 2 * t;
                const int rl0 = wm * 16 + g, rl1 = rl0 + 8;
                if (cl     > rl0) S[nt][0] = -INFINITY;
                if (cl + 1 > rl0) S[nt][1] = -INFINITY;
                if (cl     > rl1) S[nt][2] = -INFINITY;
                if (cl + 1 > rl1) S[nt][3] = -INFINITY;
            }
        }

        float rm0 = -INFINITY, rm1 = -INFINITY;
#pragma unroll
        for (int nt = 0; nt < 4; nt++) {
            rm0 = fmaxf(rm0, fmaxf(S[nt][0], S[nt][1]));
            rm1 = fmaxf(rm1, fmaxf(S[nt][2], S[nt][3]));
        }
        rm0 = fmaxf(rm0, __shfl_xor_sync(0xffffffffu, rm0, 1));
        rm0 = fmaxf(rm0, __shfl_xor_sync(0xffffffffu, rm0, 2));
        rm1 = fmaxf(rm1, __shfl_xor_sync(0xffffffffu, rm1, 1));
        rm1 = fmaxf(rm1, __shfl_xor_sync(0xffffffffu, rm1, 2));
        if (t == 0) {
            pm[wn * 64 + wm * 16 + g]     = rm0;
            pm[wn * 64 + wm * 16 + 8 + g] = rm1;
        }
        __syncthreads();
        rm0 = fmaxf(rm0, pm[(wn ^ 1) * 64 + wm * 16 + g]);
        rm1 = fmaxf(rm1, pm[(wn ^ 1) * 64 + wm * 16 + 8 + g]);

        const float mn0 = fmaxf(m0, rm0), mn1 = fmaxf(m1, rm1);
        const float a0 = __expf(m0 - mn0), a1 = __expf(m1 - mn1);

        float s0 = 0.f, s1 = 0.f;
#pragma unroll
        for (int nt = 0; nt < 4; nt++) {
            float p0 = __expf(S[nt][0] - mn0);
            float p1 = __expf(S[nt][1] - mn0);
            float p2 = __expf(S[nt][2] - mn1);
            float p3 = __expf(S[nt][3] - mn1);
            s0 += p0 + p1;
            s1 += p2 + p3;
            float h0, l0_, h1, l1_, h2, l2_, h3, l3_;
            split_tf32(p0, h0, l0_);
            split_tf32(p1, h1, l1_);
            split_tf32(p2, h2, l2_);
            split_tf32(p3, h3, l3_);
            const int col = wn * 32 + nt * 8 + 2 * t;
            const int r0 = wm * 16 + g, r1 = r0 + 8;
            *(float2*)&Ph[r0 * SC + col] = make_float2(h0, h1);
            *(float2*)&Pl[r0 * SC + col] = make_float2(l0_, l1_);
            *(float2*)&Ph[r1 * SC + col] = make_float2(h2, h3);
            *(float2*)&Pl[r1 * SC + col] = make_float2(l2_, l3_);
        }
        s0 += __shfl_xor_sync(0xffffffffu, s0, 1);
        s0 += __shfl_xor_sync(0xffffffffu, s0, 2);
        s1 += __shfl_xor_sync(0xffffffffu, s1, 1);
        s1 += __shfl_xor_sync(0xffffffffu, s1, 2);
        if (t == 0) {
            ps[wn * 64 + wm * 16 + g]     = s0;
            ps[wn * 64 + wm * 16 + 8 + g] = s1;
        }
        __syncthreads();
        l0 = l0 * a0 + ps[wm * 16 + g]     + ps[64 + wm * 16 + g];
        l1 = l1 * a1 + ps[wm * 16 + 8 + g] + ps[64 + wm * 16 + 8 + g];
        m0 = mn0; m1 = mn1;
#pragma unroll
        for (int dc = 0; dc < 4; dc++)
#pragma unroll
            for (int nt = 0; nt < 4; nt++) {
                O[dc][nt][0] *= a0; O[dc][nt][1] *= a0;
                O[dc][nt][2] *= a1; O[dc][nt][3] *= a1;
            }

        for (int dc = 0; dc < 4; dc++) {
            __syncthreads();
#pragma unroll
            for (int i = 0; i < 4; i++) {
                int f = tid + i * 256;
                int row = f >> 4, c4 = (f & 15) * 4;
                size_t src = (size_t)(k0 + row) * KD + kvh * HD + dc * 64 + c4;
                cpasync16(sb + (uint32_t)(OKH + row * SC + c4) * 4, g_Vh + src);
                cpasync16(sb + (uint32_t)(OKL + row * SC + c4) * 4, g_Vl + src);
            }
            asm volatile("cp.async.commit_group;" ::: "memory");
            asm volatile("cp.async.wait_group 0;" ::: "memory");
            __syncthreads();

#pragma unroll
            for (int kk = 0; kk < 8; kk++) {
                uint32_t ah[4], al[4];
                const int ab = (wm * 16 + g) * SC + kk * 8 + t;
                ah[0] = __float_as_uint(Ph[ab]);
                ah[1] = __float_as_uint(Ph[ab + 8 * SC]);
                ah[2] = __float_as_uint(Ph[ab + 4]);
                ah[3] = __float_as_uint(Ph[ab + 8 * SC + 4]);
                al[0] = __float_as_uint(Pl[ab]);
                al[1] = __float_as_uint(Pl[ab + 8 * SC]);
                al[2] = __float_as_uint(Pl[ab + 4]);
                al[3] = __float_as_uint(Pl[ab + 8 * SC + 4]);
#pragma unroll
                for (int nt = 0; nt < 4; nt++) {
                    const int vb = (kk * 8 + t) * SC + wn * 32 + nt * 8 + g;
                    uint32_t bh[2], bl[2];
                    bh[0] = __float_as_uint(Kh[vb]);
                    bh[1] = __float_as_uint(Kh[vb + 4 * SC]);
                    bl[0] = __float_as_uint(Kl[vb]);
                    bl[1] = __float_as_uint(Kl[vb + 4 * SC]);
                    mma8(O[dc][nt], ah, bh);
                    mma8(O[dc][nt], ah, bl);
                    mma8(O[dc][nt], al, bh);
                }
            }
        }
    }

    const float i0 = 1.0f / l0, i1 = 1.0f / l1;
#pragma unroll
    for (int dc = 0; dc < 4; dc++)
#pragma unroll
        for (int nt = 0; nt < 4; nt++) {
            const int col = h * HD + dc * 64 + wn * 32 + nt * 8 + 2 * t;
            const size_t r0 = (size_t)(t0 + wm * 16 + g) * QD + col;
            const size_t r1 = (size_t)(t0 + wm * 16 + 8 + g) * QD + col;
            *(float2*)&g_A[r0] = make_float2(O[dc][nt][0] * i0, O[dc][nt][1] * i0);
            *(float2*)&g_A[r1] = make_float2(O[dc][nt][2] * i1, O[dc][nt][3] * i1);
        }
}

// ---------------------------------------------------------------------------
// launch
// ---------------------------------------------------------------------------
extern "C" void kernel_launch(void* const* d_in, const int* in_sizes, int n_in,
                              void* d_out, int out_size)
{
    (void)in_sizes; (void)n_in; (void)out_size;
    const float* hs   = (const float*)d_in[0];
    const float* cosp = (const float*)d_in[1];
    const float* sinp = (const float*)d_in[2];
    const float* Wq   = (const float*)d_in[3];
    const float* Wk   = (const float*)d_in[4];
    const float* Wv   = (const float*)d_in[5];
    const float* Wo   = (const float*)d_in[6];
    const float* qw   = (const float*)d_in[7];
    const float* kw   = (const float*)d_in[8];
    float* out = (float*)d_out;

    float *pQ, *pK, *pV, *pA;
    float *pQh, *pQl, *pKh, *pKl, *pVh, *pVl;
    __nv_bfloat16 *phsh, *phsl, *pWqh, *pWql, *pWkh, *pWkl, *pWvh, *pWvl, *pWoh, *pWol;
    __nv_bfloat16 *pAbh, *pAbl;
    cudaGetSymbolAddress((void**)&pQ,  g_Q);
    cudaGetSymbolAddress((void**)&pK,  g_K);
    cudaGetSymbolAddress((void**)&pV,  g_V);
    cudaGetSymbolAddress((void**)&pA,  g_A);
    cudaGetSymbolAddress((void**)&pQh, g_Qh);
    cudaGetSymbolAddress((void**)&pQl, g_Ql);
    cudaGetSymbolAddress((void**)&pKh, g_Kh);
    cudaGetSymbolAddress((void**)&pKl, g_Kl);
    cudaGetSymbolAddress((void**)&pVh, g_Vh);
    cudaGetSymbolAddress((void**)&pVl, g_Vl);
    cudaGetSymbolAddress((void**)&phsh, g_hsh);
    cudaGetSymbolAddress((void**)&phsl, g_hsl);
    cudaGetSymbolAddress((void**)&pWqh, g_Wqth);
    cudaGetSymbolAddress((void**)&pWql, g_Wqtl);
    cudaGetSymbolAddress((void**)&pWkh, g_Wkth);
    cudaGetSymbolAddress((void**)&pWkl, g_Wktl);
    cudaGetSymbolAddress((void**)&pWvh, g_Wvth);
    cudaGetSymbolAddress((void**)&pWvl, g_Wvtl);
    cudaGetSymbolAddress((void**)&pWoh, g_Woth);
    cudaGetSymbolAddress((void**)&pWol, g_Wotl);
    cudaGetSymbolAddress((void**)&pAbh, g_Abh);
    cudaGetSymbolAddress((void**)&pAbl, g_Abl);

    // 0. operand prep: bf16 hi/lo split of hs + transposed split of weights
    {
        int n = L * HID / 4;
        split_bf16_kernel<<<(n + 255) / 256, 256>>>(hs, phsh, phsl, n);
    }
    transpose_split_kernel<<<dim3(QD / 32, HID / 32), dim3(32, 8)>>>(Wq, pWqh, pWql, HID, QD);
    transpose_split_kernel<<<dim3(KD / 32, HID / 32), dim3(32, 8)>>>(Wk, pWkh, pWkl, HID, KD);
    transpose_split_kernel<<<dim3(KD / 32, HID / 32), dim3(32, 8)>>>(Wv, pWvh, pWvl, HID, KD);
    transpose_split_kernel<<<dim3(HID / 32, QD / 32), dim3(32, 8)>>>(Wo, pWoh, pWol, QD, HID);

    cudaFuncSetAttribute(bf16gemm, cudaFuncAttributeMaxDynamicSharedMemorySize, BGSM);

    // 1. QKV projections (bf16-split mma.m16n8k16 + ldmatrix)
    bf16gemm<<<dim3(QD / 128, L / 128), 256, BGSM>>>(phsh, phsl, pWqh, pWql, pQ, QD, HID);
    bf16gemm<<<dim3(KD / 128, L / 128), 256, BGSM>>>(phsh, phsl, pWkh, pWkl, pK, KD, HID);
    bf16gemm<<<dim3(KD / 128, L / 128), 256, BGSM>>>(phsh, phsl, pWvh, pWvl, pV, KD, HID);

    // 2. RMSNorm + RoPE (tf32 splits for attention); V tf32 split
    norm_rope_split_kernel<<<dim3(L, NH), 256>>>(pQ, QD, qw, cosp, sinp, pQh, pQl);
    norm_rope_split_kernel<<<dim3(L, NKV), 256>>>(pK, KD, kw, cosp, sinp, pKh, pKl);
    {
        int n = L * KD / 4;
        split_tf32_kernel<<<(n + 255) / 256, 256>>>(pV, pVh, pVl, n);
    }

    // 3. attention (3xTF32 mma)
    cudaFuncSetAttribute(attn_mma_kernel,
                         cudaFuncAttributeMaxDynamicSharedMemorySize, ATT_SMEM);
    attn_mma_kernel<<<dim3(SEQ / 64, L / SEQ, NH), 256, ATT_SMEM>>>();

    // 3b. split attention output to bf16 hi/lo for out-proj
    {
        int n = L * QD / 4;
        split_bf16_kernel<<<(n + 255) / 256, 256>>>(pA, pAbh, pAbl, n);
    }

    // 4. output projection
    bf16gemm<<<dim3(HID / 128, L / 128), 256, BGSM>>>(pAbh, pAbl, pWoh, pWol, out, HID, QD);
}

// round 6
// speedup vs baseline: 2.0591x; 2.0591x over previous
#include <cuda_runtime.h>
#include <cuda_fp16.h>
#include <math.h>
#include <stdint.h>

// ---------------------------------------------------------------------------
// Problem constants
// ---------------------------------------------------------------------------
#define L     4096
#define HID   2560
#define NH    8
#define NKV   4
#define HD    256
#define QD    (NH*HD)    // 2048
#define KD    (NKV*HD)   // 1024
#define SCALING 0.0625f
#define SEQ   1024

// ---------------------------------------------------------------------------
// Scratch
// ---------------------------------------------------------------------------
__device__ float g_Q[L * QD];
__device__ float g_K[L * KD];
__device__ float g_V[L * KD];
__device__ float g_A[L * QD];
// fp16 single operands for GEMMs
__device__ __half g_hs16[L * HID];
__device__ __half g_Wq16[QD * HID];     // [N][K]
__device__ __half g_Wk16[KD * HID];
__device__ __half g_Wv16[KD * HID];
__device__ __half g_Wo16[HID * QD];
__device__ __half g_A16[L * QD];
// fp16 hi/lo splits for attention
__device__ __half g_Qh16[L * QD], g_Ql16[L * QD];
__device__ __half g_Kh16[L * KD], g_Kl16[L * KD];
__device__ __half g_Vh16[L * KD], g_Vl16[L * KD];

// ---------------------------------------------------------------------------
// helpers
// ---------------------------------------------------------------------------
__device__ __forceinline__ void mma16h(float* c, const uint32_t* a, const uint32_t* b) {
    asm volatile(
        "mma.sync.aligned.m16n8k16.row.col.f32.f16.f16.f32 "
        "{%0,%1,%2,%3}, {%4,%5,%6,%7}, {%8,%9}, {%0,%1,%2,%3};"
        : "+f"(c[0]), "+f"(c[1]), "+f"(c[2]), "+f"(c[3])
        : "r"(a[0]), "r"(a[1]), "r"(a[2]), "r"(a[3]), "r"(b[0]), "r"(b[1]));
}
__device__ __forceinline__ void ldsm4(uint32_t* r, uint32_t addr) {
    asm volatile("ldmatrix.sync.aligned.m8n8.x4.shared.b16 {%0,%1,%2,%3}, [%4];"
                 : "=r"(r[0]), "=r"(r[1]), "=r"(r[2]), "=r"(r[3]) : "r"(addr));
}
__device__ __forceinline__ void ldsm4t(uint32_t* r, uint32_t addr) {
    asm volatile("ldmatrix.sync.aligned.m8n8.x4.trans.shared.b16 {%0,%1,%2,%3}, [%4];"
                 : "=r"(r[0]), "=r"(r[1]), "=r"(r[2]), "=r"(r[3]) : "r"(addr));
}
__device__ __forceinline__ void cpasync16(uint32_t s, const void* g) {
    asm volatile("cp.async.cg.shared.global [%0], [%1], 16;" :: "r"(s), "l"(g));
}
__device__ __forceinline__ void split_h(float x, __half& h, __half& l) {
    h = __float2half_rn(x);
    l = __float2half_rn(x - __half2float(h));
}

// ---------------------------------------------------------------------------
// prep kernels
// ---------------------------------------------------------------------------
__global__ void conv_h_kernel(const float* __restrict__ in,
                              __half* __restrict__ out, int n4)
{
    int i = blockIdx.x * blockDim.x + threadIdx.x;
    if (i >= n4) return;
    float4 v = ((const float4*)in)[i];
    ((__half2*)out)[2 * i]     = __half2(__float2half_rn(v.x), __float2half_rn(v.y));
    ((__half2*)out)[2 * i + 1] = __half2(__float2half_rn(v.z), __float2half_rn(v.w));
}

__global__ void split_h_kernel(const float* __restrict__ in,
                               __half* __restrict__ oh,
                               __half* __restrict__ ol, int n4)
{
    int i = blockIdx.x * blockDim.x + threadIdx.x;
    if (i >= n4) return;
    float4 v = ((const float4*)in)[i];
    __half h0, l0, h1, l1, h2, l2, h3, l3;
    split_h(v.x, h0, l0); split_h(v.y, h1, l1);
    split_h(v.z, h2, l2); split_h(v.w, h3, l3);
    ((__half2*)oh)[2 * i]     = __half2(h0, h1);
    ((__half2*)oh)[2 * i + 1] = __half2(h2, h3);
    ((__half2*)ol)[2 * i]     = __half2(l0, l1);
    ((__half2*)ol)[2 * i + 1] = __half2(l2, l3);
}

// W[K][N] f32 -> T[N][K] fp16
__global__ void transpose_h_kernel(const float* __restrict__ W,
                                   __half* __restrict__ T, int Kdim, int Ndim)
{
    __shared__ float t[32][33];
    const int k0 = blockIdx.y * 32, n0 = blockIdx.x * 32;
    const int tx = threadIdx.x, ty = threadIdx.y;
#pragma unroll
    for (int j = 0; j < 4; j++)
        t[ty + j * 8][tx] = W[(size_t)(k0 + ty + j * 8) * Ndim + n0 + tx];
    __syncthreads();
#pragma unroll
    for (int j = 0; j < 4; j++)
        T[(size_t)(n0 + ty + j * 8) * Kdim + k0 + tx] = __float2half_rn(t[tx][ty + j * 8]);
}

// ---------------------------------------------------------------------------
// single-fp16 GEMM: C[M,Ntot](f32) = A @ B^T
//   A: [M][K] fp16 row-major; B: [Ntot][K] fp16 (pre-transposed).
// 128x128 tile / 256 thr / 8 warps (2x4), warp tile 64x32, K-chunk 32.
// ---------------------------------------------------------------------------
#define SAB 40
#define TILE_E (128*SAB)           // 5120
#define STG_E (2*TILE_E)           // A + B
#define HGSM (2*STG_E*2)           // 40960 bytes

__global__ __launch_bounds__(256)
void hgemm(const __half* __restrict__ Ap, const __half* __restrict__ Bp,
           float* __restrict__ C, int Ntot, int K)
{
    extern __shared__ __half sh16[];
    const int tid  = threadIdx.x;
    const int lane = tid & 31, wid = tid >> 5;
    const int wm = wid >> 2, wn = wid & 3;
    const int g = lane >> 2, t = lane & 3;
    const int m0 = blockIdx.y * 128, n0 = blockIdx.x * 128;

    const uint32_t sbase = (uint32_t)__cvta_generic_to_shared(sh16);
    const __half* baseA = Ap + (size_t)m0 * K;
    const __half* baseB = Bp + (size_t)n0 * K;

    float acc[4][4][4];
#pragma unroll
    for (int mt = 0; mt < 4; mt++)
#pragma unroll
        for (int nt = 0; nt < 4; nt++)
#pragma unroll
            for (int r = 0; r < 4; r++) acc[mt][nt][r] = 0.f;

    const int a_off = ((lane & 7) + ((lane >> 3) & 1) * 8) * SAB + ((lane >> 4) & 1) * 8;
    const int b_off = ((lane & 7) + ((lane >> 4) & 1) * 8) * SAB + ((lane >> 3) & 1) * 8;

    auto issue_copy = [&](int c, int buf) {
        const int koff = c * 32;
#pragma unroll
        for (int i = 0; i < 4; i++) {
            const int f = tid + i * 256;
            const int tile = f >> 9;
            const int slot = f & 511;
            const int row = slot >> 2, seg = slot & 3;
            const __half* gp = (tile ? baseB : baseA) + (size_t)row * K + koff + seg * 8;
            const uint32_t dst = sbase +
                (uint32_t)(buf * STG_E + tile * TILE_E + row * SAB + seg * 8) * 2;
            cpasync16(dst, gp);
        }
        asm volatile("cp.async.commit_group;" ::: "memory");
    };

    const int nkb = K >> 5;
    issue_copy(0, 0);

    for (int kb = 0; kb < nkb; kb++) {
        const int cur = kb & 1;
        if (kb + 1 < nkb) {
            issue_copy(kb + 1, cur ^ 1);
            asm volatile("cp.async.wait_group 1;" ::: "memory");
        } else {
            asm volatile("cp.async.wait_group 0;" ::: "memory");
        }
        __syncthreads();

        const uint32_t sA = sbase + (uint32_t)(cur * STG_E) * 2;
        const uint32_t sB = sA + (uint32_t)TILE_E * 2;

#pragma unroll
        for (int ks = 0; ks < 2; ks++) {
            const int kbase = ks * 16;
            uint32_t af[4][4], bf[2][4];
#pragma unroll
            for (int mt = 0; mt < 4; mt++)
                ldsm4(af[mt], sA + (uint32_t)((wm * 64 + mt * 16) * SAB + kbase + a_off) * 2);
#pragma unroll
            for (int np = 0; np < 2; np++)
                ldsm4(bf[np], sB + (uint32_t)((wn * 32 + np * 16) * SAB + kbase + b_off) * 2);
#pragma unroll
            for (int mt = 0; mt < 4; mt++)
#pragma unroll
                for (int nt = 0; nt < 4; nt++) {
                    const int pr = nt >> 1, hf = (nt & 1) * 2;
                    uint32_t bb[2] = { bf[pr][hf], bf[pr][hf + 1] };
                    mma16h(acc[mt][nt], af[mt], bb);
                }
        }
        __syncthreads();
    }

#pragma unroll
    for (int mt = 0; mt < 4; mt++) {
        const int r0 = m0 + wm * 64 + mt * 16 + g;
#pragma unroll
        for (int nt = 0; nt < 4; nt++) {
            const int c0 = n0 + wn * 32 + nt * 8 + t * 2;
            *(float2*)&C[(size_t)r0 * Ntot + c0] =
                make_float2(acc[mt][nt][0], acc[mt][nt][1]);
            *(float2*)&C[(size_t)(r0 + 8) * Ntot + c0] =
                make_float2(acc[mt][nt][2], acc[mt][nt][3]);
        }
    }
}

// ---------------------------------------------------------------------------
// RMSNorm + RoPE, writes fp16 hi/lo split
// ---------------------------------------------------------------------------
__global__ __launch_bounds__(256)
void norm_rope_split_kernel(const float* __restrict__ X, int hstride,
                            const float* __restrict__ w,
                            const float* __restrict__ cosp,
                            const float* __restrict__ sinp,
                            __half* __restrict__ Xh, __half* __restrict__ Xl)
{
    const int t = blockIdx.x;
    const int h = blockIdx.y;
    const int d = threadIdx.x;

    const size_t off = (size_t)t * hstride + h * HD + d;
    float x = X[off];

    float v = x * x;
#pragma unroll
    for (int o = 16; o; o >>= 1) v += __shfl_xor_sync(0xffffffffu, v, o);

    __shared__ float ws[8];
    __shared__ float buf[HD];
    if ((d & 31) == 0) ws[d >> 5] = v;
    __syncthreads();
    float ss = ws[0] + ws[1] + ws[2] + ws[3] + ws[4] + ws[5] + ws[6] + ws[7];

    float r = rsqrtf(ss * (1.0f / HD) + 1e-6f);
    float xn = x * r * (1.0f + w[d]);
    buf[d] = xn;
    __syncthreads();

    float rot = (d < HD / 2) ? -buf[d + HD / 2] : buf[d - HD / 2];
    float c = cosp[(size_t)t * HD + d];
    float s = sinp[(size_t)t * HD + d];
    float xr = xn * c + rot * s;

    __half hi, lo;
    split_h(xr, hi, lo);
    Xh[off] = hi;
    Xl[off] = lo;
}

// ---------------------------------------------------------------------------
// Flash attention, fp16 hi/lo split (3-product) on mma.m16n8k16 + ldmatrix.
// Block 256 thr / 8 warps (4x2): warp = 16 q-rows x 32 k-cols (or d-cols).
// Tile 64q x 64k, d-chunks of 64.
// ---------------------------------------------------------------------------
#define SQF 264
#define SCF 72
#define OQH2 0
#define OQL2 (64*SQF)
#define OKH2 (2*64*SQF)
#define OKL2 (OKH2 + 64*SCF)
#define OPH2 (OKL2 + 64*SCF)
#define OPL2 (OPH2 + 64*SCF)
#define OEND2 (OPL2 + 64*SCF)
#define ATTH_SMEM (OEND2*2 + 256*4)

__global__ __launch_bounds__(256, 1)
void attn_h_kernel()
{
    extern __shared__ __half smh[];
    float* pm = (float*)(smh + OEND2);        // [2][64]
    float* ps = pm + 128;                     // [2][64]

    const int qt  = blockIdx.x;
    const int seq = blockIdx.y;
    const int h   = blockIdx.z;
    const int kvh = h >> 1;

    const int tid  = threadIdx.x;
    const int lane = tid & 31, wid = tid >> 5;
    const int wm = wid >> 1, wn = wid & 1;    // 4 x 2
    const int g = lane >> 2, t = lane & 3;

    const int t0 = seq * SEQ + qt * 64;
    const uint32_t sb = (uint32_t)__cvta_generic_to_shared(smh);

    const int aoffQ = ((lane & 7) + ((lane >> 3) & 1) * 8) * SQF + ((lane >> 4) & 1) * 8;
    const int aoffP = ((lane & 7) + ((lane >> 3) & 1) * 8) * SCF + ((lane >> 4) & 1) * 8;
    const int boffK = ((lane & 7) + ((lane >> 4) & 1) * 8) * SCF + ((lane >> 3) & 1) * 8;
    const int voffV = aoffP;   // same formula, used with .trans for V

    // resident Q hi/lo (fp16): 2 tiles x 64 rows x 32 segs
    {
        const __half* gqh = g_Qh16 + (size_t)t0 * QD + h * HD;
        const __half* gql = g_Ql16 + (size_t)t0 * QD + h * HD;
#pragma unroll
        for (int i = 0; i < 16; i++) {
            int f = tid + i * 256;
            int tile = f >> 11;
            int slot = f & 2047;
            int row = slot >> 5, seg = slot & 31;
            const __half* gp = (tile ? gql : gqh) + (size_t)row * QD + seg * 8;
            cpasync16(sb + (uint32_t)((tile ? OQL2 : OQH2) + row * SQF + seg * 8) * 2, gp);
        }
        asm volatile("cp.async.commit_group;" ::: "memory");
        asm volatile("cp.async.wait_group 0;" ::: "memory");
    }
    __syncthreads();

    float O[4][4][4];
#pragma unroll
    for (int dc = 0; dc < 4; dc++)
#pragma unroll
        for (int nt = 0; nt < 4; nt++)
#pragma unroll
            for (int r = 0; r < 4; r++) O[dc][nt][r] = 0.f;
    float m0 = -INFINITY, m1 = -INFINITY, l0 = 0.f, l1 = 0.f;

    for (int kt = 0; kt <= qt; kt++) {
        const int k0 = seq * SEQ + kt * 64;

        float S[4][4];
#pragma unroll
        for (int nt = 0; nt < 4; nt++)
#pragma unroll
            for (int r = 0; r < 4; r++) S[nt][r] = 0.f;

        // ---- S = Q @ K^T over 4 d-chunks ----
        for (int dc = 0; dc < 4; dc++) {
            __syncthreads();
#pragma unroll
            for (int i = 0; i < 4; i++) {
                int f = tid + i * 256;
                int tile = f >> 9;
                int slot = f & 511;
                int row = slot >> 3, seg = slot & 7;
                const __half* gp = (tile ? g_Kl16 : g_Kh16) +
                    (size_t)(k0 + row) * KD + kvh * HD + dc * 64 + seg * 8;
                cpasync16(sb + (uint32_t)((tile ? OKL2 : OKH2) + row * SCF + seg * 8) * 2, gp);
            }
            asm volatile("cp.async.commit_group;" ::: "memory");
            asm volatile("cp.async.wait_group 0;" ::: "memory");
            __syncthreads();

#pragma unroll
            for (int ks = 0; ks < 4; ks++) {
                const int kq = dc * 64 + ks * 16;
                uint32_t qh[4], ql[4], kh[2][4], kl[2][4];
                ldsm4(qh, sb + (uint32_t)(OQH2 + (wm * 16) * SQF + kq + aoffQ) * 2);
                ldsm4(ql, sb + (uint32_t)(OQL2 + (wm * 16) * SQF + kq + aoffQ) * 2);
#pragma unroll
                for (int pr = 0; pr < 2; pr++) {
                    const int nb = (wn * 32 + pr * 16) * SCF + ks * 16;
                    ldsm4(kh[pr], sb + (uint32_t)(OKH2 + nb + boffK) * 2);
                    ldsm4(kl[pr], sb + (uint32_t)(OKL2 + nb + boffK) * 2);
                }
#pragma unroll
                for (int nt = 0; nt < 4; nt++) {
                    const int pr = nt >> 1, hf = (nt & 1) * 2;
                    uint32_t bH[2] = { kh[pr][hf], kh[pr][hf + 1] };
                    uint32_t bL[2] = { kl[pr][hf], kl[pr][hf + 1] };
                    mma16h(S[nt], qh, bH);
                    mma16h(S[nt], qh, bL);
                    mma16h(S[nt], ql, bH);
                }
            }
        }

        // ---- scale + causal mask ----
#pragma unroll
        for (int nt = 0; nt < 4; nt++) {
#pragma unroll
            for (int r = 0; r < 4; r++) S[nt][r] *= SCALING;
            if (kt == qt) {
                const int cl = wn * 32 + nt * 8 + 2 * t;
                const int rl0 = wm * 16 + g, rl1 = rl0 + 8;
                if (cl     > rl0) S[nt][0] = -INFINITY;
                if (cl + 1 > rl0) S[nt][1] = -INFINITY;
                if (cl     > rl1) S[nt][2] = -INFINITY;
                if (cl + 1 > rl1) S[nt][3] = -INFINITY;
            }
        }

        // ---- online softmax ----
        float rm0 = -INFINITY, rm1 = -INFINITY;
#pragma unroll
        for (int nt = 0; nt < 4; nt++) {
            rm0 = fmaxf(rm0, fmaxf(S[nt][0], S[nt][1]));
            rm1 = fmaxf(rm1, fmaxf(S[nt][2], S[nt][3]));
        }
        rm0 = fmaxf(rm0, __shfl_xor_sync(0xffffffffu, rm0, 1));
        rm0 = fmaxf(rm0, __shfl_xor_sync(0xffffffffu, rm0, 2));
        rm1 = fmaxf(rm1, __shfl_xor_sync(0xffffffffu, rm1, 1));
        rm1 = fmaxf(rm1, __shfl_xor_sync(0xffffffffu, rm1, 2));
        if (t == 0) {
            pm[wn * 64 + wm * 16 + g]     = rm0;
            pm[wn * 64 + wm * 16 + 8 + g] = rm1;
        }
        __syncthreads();
        rm0 = fmaxf(rm0, pm[(wn ^ 1) * 64 + wm * 16 + g]);
        rm1 = fmaxf(rm1, pm[(wn ^ 1) * 64 + wm * 16 + 8 + g]);

        const float mn0 = fmaxf(m0, rm0), mn1 = fmaxf(m1, rm1);
        const float a0 = __expf(m0 - mn0), a1 = __expf(m1 - mn1);

        float s0 = 0.f, s1 = 0.f;
#pragma unroll
        for (int nt = 0; nt < 4; nt++) {
            float p0 = __expf(S[nt][0] - mn0);
            float p1 = __expf(S[nt][1] - mn0);
            float p2 = __expf(S[nt][2] - mn1);
            float p3 = __expf(S[nt][3] - mn1);
            s0 += p0 + p1;
            s1 += p2 + p3;
            __half h0, l0_, h1, l1_, h2, l2_, h3, l3_;
            split_h(p0, h0, l0_); split_h(p1, h1, l1_);
            split_h(p2, h2, l2_); split_h(p3, h3, l3_);
            const int col = wn * 32 + nt * 8 + 2 * t;
            const int r0 = wm * 16 + g, r1 = r0 + 8;
            *(__half2*)&smh[OPH2 + r0 * SCF + col] = __half2(h0, h1);
            *(__half2*)&smh[OPL2 + r0 * SCF + col] = __half2(l0_, l1_);
            *(__half2*)&smh[OPH2 + r1 * SCF + col] = __half2(h2, h3);
            *(__half2*)&smh[OPL2 + r1 * SCF + col] = __half2(l2_, l3_);
        }
        s0 += __shfl_xor_sync(0xffffffffu, s0, 1);
        s0 += __shfl_xor_sync(0xffffffffu, s0, 2);
        s1 += __shfl_xor_sync(0xffffffffu, s1, 1);
        s1 += __shfl_xor_sync(0xffffffffu, s1, 2);
        if (t == 0) {
            ps[wn * 64 + wm * 16 + g]     = s0;
            ps[wn * 64 + wm * 16 + 8 + g] = s1;
        }
        __syncthreads();
        l0 = l0 * a0 + ps[wm * 16 + g]     + ps[64 + wm * 16 + g];
        l1 = l1 * a1 + ps[wm * 16 + 8 + g] + ps[64 + wm * 16 + 8 + g];
        m0 = mn0; m1 = mn1;
#pragma unroll
        for (int dc = 0; dc < 4; dc++)
#pragma unroll
            for (int nt = 0; nt < 4; nt++) {
                O[dc][nt][0] *= a0; O[dc][nt][1] *= a0;
                O[dc][nt][2] *= a1; O[dc][nt][3] *= a1;
            }

        // ---- O += P @ V over 4 d-chunks (V in K slot, ldmatrix.trans) ----
        for (int dc = 0; dc < 4; dc++) {
            __syncthreads();
#pragma unroll
            for (int i = 0; i < 4; i++) {
                int f = tid + i * 256;
                int tile = f >> 9;
                int slot = f & 511;
                int row = slot >> 3, seg = slot & 7;
                const __half* gp = (tile ? g_Vl16 : g_Vh16) +
                    (size_t)(k0 + row) * KD + kvh * HD + dc * 64 + seg * 8;
                cpasync16(sb + (uint32_t)((tile ? OKL2 : OKH2) + row * SCF + seg * 8) * 2, gp);
            }
            asm volatile("cp.async.commit_group;" ::: "memory");
            asm volatile("cp.async.wait_group 0;" ::: "memory");
            __syncthreads();

#pragma unroll
            for (int kk = 0; kk < 4; kk++) {
                uint32_t ph[4], pl[4], vh[2][4], vl[2][4];
                ldsm4(ph, sb + (uint32_t)(OPH2 + (wm * 16) * SCF + kk * 16 + aoffP) * 2);
                ldsm4(pl, sb + (uint32_t)(OPL2 + (wm * 16) * SCF + kk * 16 + aoffP) * 2);
#pragma unroll
                for (int pr = 0; pr < 2; pr++) {
                    const int vb = (kk * 16) * SCF + wn * 32 + pr * 16;
                    ldsm4t(vh[pr], sb + (uint32_t)(OKH2 + vb + voffV) * 2);
                    ldsm4t(vl[pr], sb + (uint32_t)(OKL2 + vb + voffV) * 2);
                }
#pragma unroll
                for (int nt = 0; nt < 4; nt++) {
                    const int pr = nt >> 1, hf = (nt & 1) * 2;
                    uint32_t bH[2] = { vh[pr][hf], vh[pr][hf + 1] };
                    uint32_t bL[2] = { vl[pr][hf], vl[pr][hf + 1] };
                    mma16h(O[dc][nt], ph, bH);
                    mma16h(O[dc][nt], ph, bL);
                    mma16h(O[dc][nt], pl, bH);
                }
            }
        }
    }

    // ---- epilogue ----
    const float i0 = 1.0f / l0, i1 = 1.0f / l1;
#pragma unroll
    for (int dc = 0; dc < 4; dc++)
#pragma unroll
        for (int nt = 0; nt < 4; nt++) {
            const int col = h * HD + dc * 64 + wn * 32 + nt * 8 + 2 * t;
            const size_t r0 = (size_t)(t0 + wm * 16 + g) * QD + col;
            const size_t r1 = (size_t)(t0 + wm * 16 + 8 + g) * QD + col;
            *(float2*)&g_A[r0] = make_float2(O[dc][nt][0] * i0, O[dc][nt][1] * i0);
            *(float2*)&g_A[r1] = make_float2(O[dc][nt][2] * i1, O[dc][nt][3] * i1);
        }
}

// ---------------------------------------------------------------------------
// launch
// ---------------------------------------------------------------------------
extern "C" void kernel_launch(void* const* d_in, const int* in_sizes, int n_in,
                              void* d_out, int out_size)
{
    (void)in_sizes; (void)n_in; (void)out_size;
    const float* hs   = (const float*)d_in[0];
    const float* cosp = (const float*)d_in[1];
    const float* sinp = (const float*)d_in[2];
    const float* Wq   = (const float*)d_in[3];
    const float* Wk   = (const float*)d_in[4];
    const float* Wv   = (const float*)d_in[5];
    const float* Wo   = (const float*)d_in[6];
    const float* qw   = (const float*)d_in[7];
    const float* kw   = (const float*)d_in[8];
    float* out = (float*)d_out;

    float *pQ, *pK, *pV, *pA;
    __half *phs, *pWq, *pWk, *pWv, *pWo, *pA16;
    __half *pQh, *pQl, *pKh, *pKl, *pVh, *pVl;
    cudaGetSymbolAddress((void**)&pQ,   g_Q);
    cudaGetSymbolAddress((void**)&pK,   g_K);
    cudaGetSymbolAddress((void**)&pV,   g_V);
    cudaGetSymbolAddress((void**)&pA,   g_A);
    cudaGetSymbolAddress((void**)&phs,  g_hs16);
    cudaGetSymbolAddress((void**)&pWq,  g_Wq16);
    cudaGetSymbolAddress((void**)&pWk,  g_Wk16);
    cudaGetSymbolAddress((void**)&pWv,  g_Wv16);
    cudaGetSymbolAddress((void**)&pWo,  g_Wo16);
    cudaGetSymbolAddress((void**)&pA16, g_A16);
    cudaGetSymbolAddress((void**)&pQh,  g_Qh16);
    cudaGetSymbolAddress((void**)&pQl,  g_Ql16);
    cudaGetSymbolAddress((void**)&pKh,  g_Kh16);
    cudaGetSymbolAddress((void**)&pKl,  g_Kl16);
    cudaGetSymbolAddress((void**)&pVh,  g_Vh16);
    cudaGetSymbolAddress((void**)&pVl,  g_Vl16);

    // 0. operand prep
    {
        int n = L * HID / 4;
        conv_h_kernel<<<(n + 255) / 256, 256>>>(hs, phs, n);
    }
    transpose_h_kernel<<<dim3(QD / 32, HID / 32), dim3(32, 8)>>>(Wq, pWq, HID, QD);
    transpose_h_kernel<<<dim3(KD / 32, HID / 32), dim3(32, 8)>>>(Wk, pWk, HID, KD);
    transpose_h_kernel<<<dim3(KD / 32, HID / 32), dim3(32, 8)>>>(Wv, pWv, HID, KD);
    transpose_h_kernel<<<dim3(HID / 32, QD / 32), dim3(32, 8)>>>(Wo, pWo, QD, HID);

    cudaFuncSetAttribute(hgemm, cudaFuncAttributeMaxDynamicSharedMemorySize, HGSM);

    // 1. QKV projections (single fp16 mma16)
    hgemm<<<dim3(QD / 128, L / 128), 256, HGSM>>>(phs, pWq, pQ, QD, HID);
    hgemm<<<dim3(KD / 128, L / 128), 256, HGSM>>>(phs, pWk, pK, KD, HID);
    hgemm<<<dim3(KD / 128, L / 128), 256, HGSM>>>(phs, pWv, pV, KD, HID);

    // 2. RMSNorm + RoPE -> fp16 hi/lo; V fp16 split
    norm_rope_split_kernel<<<dim3(L, NH), 256>>>(pQ, QD, qw, cosp, sinp, pQh, pQl);
    norm_rope_split_kernel<<<dim3(L, NKV), 256>>>(pK, KD, kw, cosp, sinp, pKh, pKl);
    {
        int n = L * KD / 4;
        split_h_kernel<<<(n + 255) / 256, 256>>>(pV, pVh, pVl, n);
    }

    // 3. attention (fp16-split mma16 + ldmatrix)
    cudaFuncSetAttribute(attn_h_kernel,
                         cudaFuncAttributeMaxDynamicSharedMemorySize, ATTH_SMEM);
    attn_h_kernel<<<dim3(SEQ / 64, L / SEQ, NH), 256, ATTH_SMEM>>>();

    // 3b. A -> fp16 for out-proj
    {
        int n = L * QD / 4;
        conv_h_kernel<<<(n + 255) / 256, 256>>>(pA, pA16, n);
    }

    // 4. output projection
    hgemm<<<dim3(HID / 128, L / 128), 256, HGSM>>>(pA16, pWo, out, HID, QD);
}

// round 7
// speedup vs baseline: 2.4197x; 1.1751x over previous
#include <cuda_runtime.h>
#include <cuda_fp16.h>
#include <math.h>
#include <stdint.h>

// ---------------------------------------------------------------------------
// Problem constants
// ---------------------------------------------------------------------------
#define L     4096
#define HID   2560
#define NH    8
#define NKV   4
#define HD    256
#define QD    (NH*HD)    // 2048
#define KD    (NKV*HD)   // 1024
#define QKVD  (QD + 2*KD) // 4096
#define SCALING 0.0625f
#define SEQ   1024

// ---------------------------------------------------------------------------
// Scratch
// ---------------------------------------------------------------------------
__device__ float g_QKV[L * QKVD];     // fused projection output [t][4096]
__device__ float g_A[L * QD];
__device__ __half g_hs16[L * HID];
__device__ __half g_Wqkv16[QKVD * HID];  // [N][K] transposed, Q|K|V rows
__device__ __half g_Wo16[HID * QD];
__device__ __half g_A16[L * QD];
// fp16 hi/lo splits for attention
__device__ __half g_Qh16[L * QD], g_Ql16[L * QD];
__device__ __half g_Kh16[L * KD], g_Kl16[L * KD];
__device__ __half g_Vh16[L * KD], g_Vl16[L * KD];

// ---------------------------------------------------------------------------
// helpers
// ---------------------------------------------------------------------------
__device__ __forceinline__ void mma16h(float* c, const uint32_t* a, const uint32_t* b) {
    asm volatile(
        "mma.sync.aligned.m16n8k16.row.col.f32.f16.f16.f32 "
        "{%0,%1,%2,%3}, {%4,%5,%6,%7}, {%8,%9}, {%0,%1,%2,%3};"
        : "+f"(c[0]), "+f"(c[1]), "+f"(c[2]), "+f"(c[3])
        : "r"(a[0]), "r"(a[1]), "r"(a[2]), "r"(a[3]), "r"(b[0]), "r"(b[1]));
}
__device__ __forceinline__ void ldsm4(uint32_t* r, uint32_t addr) {
    asm volatile("ldmatrix.sync.aligned.m8n8.x4.shared.b16 {%0,%1,%2,%3}, [%4];"
                 : "=r"(r[0]), "=r"(r[1]), "=r"(r[2]), "=r"(r[3]) : "r"(addr));
}
__device__ __forceinline__ void ldsm4t(uint32_t* r, uint32_t addr) {
    asm volatile("ldmatrix.sync.aligned.m8n8.x4.trans.shared.b16 {%0,%1,%2,%3}, [%4];"
                 : "=r"(r[0]), "=r"(r[1]), "=r"(r[2]), "=r"(r[3]) : "r"(addr));
}
__device__ __forceinline__ void cpasync16(uint32_t s, const void* g) {
    asm volatile("cp.async.cg.shared.global [%0], [%1], 16;" :: "r"(s), "l"(g));
}
__device__ __forceinline__ void split_h(float x, __half& h, __half& l) {
    h = __float2half_rn(x);
    l = __float2half_rn(x - __half2float(h));
}

// ---------------------------------------------------------------------------
// prep kernels
// ---------------------------------------------------------------------------
__global__ void conv_h_kernel(const float* __restrict__ in,
                              __half* __restrict__ out, int n4)
{
    int i = blockIdx.x * blockDim.x + threadIdx.x;
    if (i >= n4) return;
    float4 v = ((const float4*)in)[i];
    ((__half2*)out)[2 * i]     = __half2(__float2half_rn(v.x), __float2half_rn(v.y));
    ((__half2*)out)[2 * i + 1] = __half2(__float2half_rn(v.z), __float2half_rn(v.w));
}

// strided split for V inside the fused QKV buffer
__global__ void split_h_strided_kernel(const float* __restrict__ in,  // + col offset
                                       __half* __restrict__ oh,
                                       __half* __restrict__ ol, int n4)
{
    int i = blockIdx.x * blockDim.x + threadIdx.x;
    if (i >= n4) return;
    const int row = i >> 8;                 // KD/4 = 256 float4 per row
    const int col = i & 255;
    float4 v = ((const float4*)(in + (size_t)row * QKVD))[col];
    __half h0, l0, h1, l1, h2, l2, h3, l3;
    split_h(v.x, h0, l0); split_h(v.y, h1, l1);
    split_h(v.z, h2, l2); split_h(v.w, h3, l3);
    ((__half2*)oh)[2 * i]     = __half2(h0, h1);
    ((__half2*)oh)[2 * i + 1] = __half2(h2, h3);
    ((__half2*)ol)[2 * i]     = __half2(l0, l1);
    ((__half2*)ol)[2 * i + 1] = __half2(l2, l3);
}

// W[K][N] f32 -> T[N][K] fp16
__global__ void transpose_h_kernel(const float* __restrict__ W,
                                   __half* __restrict__ T, int Kdim, int Ndim)
{
    __shared__ float t[32][33];
    const int k0 = blockIdx.y * 32, n0 = blockIdx.x * 32;
    const int tx = threadIdx.x, ty = threadIdx.y;
#pragma unroll
    for (int j = 0; j < 4; j++)
        t[ty + j * 8][tx] = W[(size_t)(k0 + ty + j * 8) * Ndim + n0 + tx];
    __syncthreads();
#pragma unroll
    for (int j = 0; j < 4; j++)
        T[(size_t)(n0 + ty + j * 8) * Kdim + k0 + tx] = __float2half_rn(t[tx][ty + j * 8]);
}

// ---------------------------------------------------------------------------
// single-fp16 GEMM, 2 CTAs/SM: C[M,Ntot](f32) = A @ B^T
// ---------------------------------------------------------------------------
#define SAB 40
#define TILE_E (128*SAB)
#define STG_E (2*TILE_E)
#define HGSM (2*STG_E*2)           // 40960 bytes

__global__ __launch_bounds__(256, 2)
void hgemm(const __half* __restrict__ Ap, const __half* __restrict__ Bp,
           float* __restrict__ C, int Ntot, int K)
{
    extern __shared__ __half sh16[];
    const int tid  = threadIdx.x;
    const int lane = tid & 31, wid = tid >> 5;
    const int wm = wid >> 2, wn = wid & 3;
    const int g = lane >> 2, t = lane & 3;
    const int m0 = blockIdx.y * 128, n0 = blockIdx.x * 128;

    const uint32_t sbase = (uint32_t)__cvta_generic_to_shared(sh16);
    const __half* baseA = Ap + (size_t)m0 * K;
    const __half* baseB = Bp + (size_t)n0 * K;

    float acc[4][4][4];
#pragma unroll
    for (int mt = 0; mt < 4; mt++)
#pragma unroll
        for (int nt = 0; nt < 4; nt++)
#pragma unroll
            for (int r = 0; r < 4; r++) acc[mt][nt][r] = 0.f;

    const int a_off = ((lane & 7) + ((lane >> 3) & 1) * 8) * SAB + ((lane >> 4) & 1) * 8;
    const int b_off = ((lane & 7) + ((lane >> 4) & 1) * 8) * SAB + ((lane >> 3) & 1) * 8;

    auto issue_copy = [&](int c, int buf) {
        const int koff = c * 32;
#pragma unroll
        for (int i = 0; i < 4; i++) {
            const int f = tid + i * 256;
            const int tile = f >> 9;
            const int slot = f & 511;
            const int row = slot >> 2, seg = slot & 3;
            const __half* gp = (tile ? baseB : baseA) + (size_t)row * K + koff + seg * 8;
            const uint32_t dst = sbase +
                (uint32_t)(buf * STG_E + tile * TILE_E + row * SAB + seg * 8) * 2;
            cpasync16(dst, gp);
        }
        asm volatile("cp.async.commit_group;" ::: "memory");
    };

    const int nkb = K >> 5;
    issue_copy(0, 0);

    for (int kb = 0; kb < nkb; kb++) {
        const int cur = kb & 1;
        if (kb + 1 < nkb) {
            issue_copy(kb + 1, cur ^ 1);
            asm volatile("cp.async.wait_group 1;" ::: "memory");
        } else {
            asm volatile("cp.async.wait_group 0;" ::: "memory");
        }
        __syncthreads();

        const uint32_t sA = sbase + (uint32_t)(cur * STG_E) * 2;
        const uint32_t sB = sA + (uint32_t)TILE_E * 2;

#pragma unroll
        for (int ks = 0; ks < 2; ks++) {
            const int kbase = ks * 16;
            uint32_t af[4][4], bf[2][4];
#pragma unroll
            for (int mt = 0; mt < 4; mt++)
                ldsm4(af[mt], sA + (uint32_t)((wm * 64 + mt * 16) * SAB + kbase + a_off) * 2);
#pragma unroll
            for (int np = 0; np < 2; np++)
                ldsm4(bf[np], sB + (uint32_t)((wn * 32 + np * 16) * SAB + kbase + b_off) * 2);
#pragma unroll
            for (int mt = 0; mt < 4; mt++)
#pragma unroll
                for (int nt = 0; nt < 4; nt++) {
                    const int pr = nt >> 1, hf = (nt & 1) * 2;
                    uint32_t bb[2] = { bf[pr][hf], bf[pr][hf + 1] };
                    mma16h(acc[mt][nt], af[mt], bb);
                }
        }
        __syncthreads();
    }

#pragma unroll
    for (int mt = 0; mt < 4; mt++) {
        const int r0 = m0 + wm * 64 + mt * 16 + g;
#pragma unroll
        for (int nt = 0; nt < 4; nt++) {
            const int c0 = n0 + wn * 32 + nt * 8 + t * 2;
            *(float2*)&C[(size_t)r0 * Ntot + c0] =
                make_float2(acc[mt][nt][0], acc[mt][nt][1]);
            *(float2*)&C[(size_t)(r0 + 8) * Ntot + c0] =
                make_float2(acc[mt][nt][2], acc[mt][nt][3]);
        }
    }
}

// ---------------------------------------------------------------------------
// RMSNorm + RoPE, writes fp16 hi/lo split (X strided into fused QKV buffer)
// ---------------------------------------------------------------------------
__global__ __launch_bounds__(256)
void norm_rope_split_kernel(const float* __restrict__ X, int hstride,
                            const float* __restrict__ w,
                            const float* __restrict__ cosp,
                            const float* __restrict__ sinp,
                            __half* __restrict__ Xh, __half* __restrict__ Xl,
                            int ostride)
{
    const int t = blockIdx.x;
    const int h = blockIdx.y;
    const int d = threadIdx.x;

    float x = X[(size_t)t * hstride + h * HD + d];

    float v = x * x;
#pragma unroll
    for (int o = 16; o; o >>= 1) v += __shfl_xor_sync(0xffffffffu, v, o);

    __shared__ float ws[8];
    __shared__ float buf[HD];
    if ((d & 31) == 0) ws[d >> 5] = v;
    __syncthreads();
    float ss = ws[0] + ws[1] + ws[2] + ws[3] + ws[4] + ws[5] + ws[6] + ws[7];

    float r = rsqrtf(ss * (1.0f / HD) + 1e-6f);
    float xn = x * r * (1.0f + w[d]);
    buf[d] = xn;
    __syncthreads();

    float rot = (d < HD / 2) ? -buf[d + HD / 2] : buf[d - HD / 2];
    float c = cosp[(size_t)t * HD + d];
    float s = sinp[(size_t)t * HD + d];
    float xr = xn * c + rot * s;

    __half hi, lo;
    split_h(xr, hi, lo);
    const size_t oo = (size_t)t * ostride + h * HD + d;
    Xh[oo] = hi;
    Xl[oo] = lo;
}

// ---------------------------------------------------------------------------
// Flash attention, fp16 hi/lo split, double-buffered K/V chunk pipeline.
// ---------------------------------------------------------------------------
#define SQF 264
#define SCF 72
#define CHUNK_E (64*SCF)                  // 4608 elems per chunk tile
#define OQH2 0
#define OQL2 (64*SQF)
#define OCH  (2*64*SQF)                   // 4 chunk slots: [buf][h/l]
#define OPH2 (OCH + 4*CHUNK_E)
#define OPL2 (OPH2 + CHUNK_E)
#define OEND2 (OPL2 + CHUNK_E)
#define ATTH_SMEM (OEND2*2 + 256*4)

__global__ __launch_bounds__(256, 1)
void attn_h_kernel()
{
    extern __shared__ __half smh[];
    float* pm = (float*)(smh + OEND2);
    float* ps = pm + 128;

    const int qt  = (int)gridDim.x - 1 - (int)blockIdx.x;  // long diagonals first
    const int seq = blockIdx.y;
    const int h   = blockIdx.z;
    const int kvh = h >> 1;

    const int tid  = threadIdx.x;
    const int lane = tid & 31, wid = tid >> 5;
    const int wm = wid >> 1, wn = wid & 1;
    const int g = lane >> 2, t = lane & 3;

    const int t0 = seq * SEQ + qt * 64;
    const uint32_t sb = (uint32_t)__cvta_generic_to_shared(smh);

    const int aoffQ = ((lane & 7) + ((lane >> 3) & 1) * 8) * SQF + ((lane >> 4) & 1) * 8;
    const int aoffP = ((lane & 7) + ((lane >> 3) & 1) * 8) * SCF + ((lane >> 4) & 1) * 8;
    const int boffK = ((lane & 7) + ((lane >> 4) & 1) * 8) * SCF + ((lane >> 3) & 1) * 8;
    const int voffV = aoffP;

    // chunk loader: hi/lo pair of 64x64 fp16 into slot buf
    auto issue_kv = [&](const __half* gh, const __half* gl, int k0, int dc, int buf) {
#pragma unroll
        for (int i = 0; i < 4; i++) {
            int f = tid + i * 256;
            int tile = f >> 9;
            int slot = f & 511;
            int row = slot >> 3, seg = slot & 7;
            const __half* gp = (tile ? gl : gh) +
                (size_t)(k0 + row) * KD + kvh * HD + dc * 64 + seg * 8;
            cpasync16(sb + (uint32_t)(OCH + (buf * 2 + tile) * CHUNK_E + row * SCF + seg * 8) * 2, gp);
        }
        asm volatile("cp.async.commit_group;" ::: "memory");
    };

    // resident Q hi/lo
    {
        const __half* gqh = g_Qh16 + (size_t)t0 * QD + h * HD;
        const __half* gql = g_Ql16 + (size_t)t0 * QD + h * HD;
#pragma unroll
        for (int i = 0; i < 16; i++) {
            int f = tid + i * 256;
            int tile = f >> 11;
            int slot = f & 2047;
            int row = slot >> 5, seg = slot & 31;
            const __half* gp = (tile ? gql : gqh) + (size_t)row * QD + seg * 8;
            cpasync16(sb + (uint32_t)((tile ? OQL2 : OQH2) + row * SQF + seg * 8) * 2, gp);
        }
        asm volatile("cp.async.commit_group;" ::: "memory");
        asm volatile("cp.async.wait_group 0;" ::: "memory");
    }
    __syncthreads();

    float O[4][4][4];
#pragma unroll
    for (int dc = 0; dc < 4; dc++)
#pragma unroll
        for (int nt = 0; nt < 4; nt++)
#pragma unroll
            for (int r = 0; r < 4; r++) O[dc][nt][r] = 0.f;
    float m0 = -INFINITY, m1 = -INFINITY, l0 = 0.f, l1 = 0.f;

    for (int kt = 0; kt <= qt; kt++) {
        const int k0 = seq * SEQ + kt * 64;

        float S[4][4];
#pragma unroll
        for (int nt = 0; nt < 4; nt++)
#pragma unroll
            for (int r = 0; r < 4; r++) S[nt][r] = 0.f;

        // ---- S = Q @ K^T, pipelined over 4 d-chunks ----
        issue_kv(g_Kh16, g_Kl16, k0, 0, 0);
        for (int dc = 0; dc < 4; dc++) {
            const int buf = dc & 1;
            if (dc < 3) {
                issue_kv(g_Kh16, g_Kl16, k0, dc + 1, buf ^ 1);
                asm volatile("cp.async.wait_group 1;" ::: "memory");
            } else {
                asm volatile("cp.async.wait_group 0;" ::: "memory");
            }
            __syncthreads();

            const int okh = OCH + buf * 2 * CHUNK_E;
            const int okl = okh + CHUNK_E;
#pragma unroll
            for (int ks = 0; ks < 4; ks++) {
                const int kq = dc * 64 + ks * 16;
                uint32_t qh[4], ql[4], kh[2][4], kl[2][4];
                ldsm4(qh, sb + (uint32_t)(OQH2 + (wm * 16) * SQF + kq + aoffQ) * 2);
                ldsm4(ql, sb + (uint32_t)(OQL2 + (wm * 16) * SQF + kq + aoffQ) * 2);
#pragma unroll
                for (int pr = 0; pr < 2; pr++) {
                    const int nb = (wn * 32 + pr * 16) * SCF + ks * 16;
                    ldsm4(kh[pr], sb + (uint32_t)(okh + nb + boffK) * 2);
                    ldsm4(kl[pr], sb + (uint32_t)(okl + nb + boffK) * 2);
                }
#pragma unroll
                for (int nt = 0; nt < 4; nt++) {
                    const int pr = nt >> 1, hf = (nt & 1) * 2;
                    uint32_t bH[2] = { kh[pr][hf], kh[pr][hf + 1] };
                    uint32_t bL[2] = { kl[pr][hf], kl[pr][hf + 1] };
                    mma16h(S[nt], qh, bH);
                    mma16h(S[nt], qh, bL);
                    mma16h(S[nt], ql, bH);
                }
            }
            __syncthreads();
        }

        // ---- scale + causal mask ----
#pragma unroll
        for (int nt = 0; nt < 4; nt++) {
#pragma unroll
            for (int r = 0; r < 4; r++) S[nt][r] *= SCALING;
            if (kt == qt) {
                const int cl = wn * 32 + nt * 8 + 2 * t;
                const int rl0 = wm * 16 + g, rl1 = rl0 + 8;
                if (cl     > rl0) S[nt][0] = -INFINITY;
                if (cl + 1 > rl0) S[nt][1] = -INFINITY;
                if (cl     > rl1) S[nt][2] = -INFINITY;
                if (cl + 1 > rl1) S[nt][3] = -INFINITY;
            }
        }

        // ---- online softmax ----
        float rm0 = -INFINITY, rm1 = -INFINITY;
#pragma unroll
        for (int nt = 0; nt < 4; nt++) {
            rm0 = fmaxf(rm0, fmaxf(S[nt][0], S[nt][1]));
            rm1 = fmaxf(rm1, fmaxf(S[nt][2], S[nt][3]));
        }
        rm0 = fmaxf(rm0, __shfl_xor_sync(0xffffffffu, rm0, 1));
        rm0 = fmaxf(rm0, __shfl_xor_sync(0xffffffffu, rm0, 2));
        rm1 = fmaxf(rm1, __shfl_xor_sync(0xffffffffu, rm1, 1));
        rm1 = fmaxf(rm1, __shfl_xor_sync(0xffffffffu, rm1, 2));
        if (t == 0) {
            pm[wn * 64 + wm * 16 + g]     = rm0;
            pm[wn * 64 + wm * 16 + 8 + g] = rm1;
        }
        __syncthreads();
        rm0 = fmaxf(rm0, pm[(wn ^ 1) * 64 + wm * 16 + g]);
        rm1 = fmaxf(rm1, pm[(wn ^ 1) * 64 + wm * 16 + 8 + g]);

        const float mn0 = fmaxf(m0, rm0), mn1 = fmaxf(m1, rm1);
        const float a0 = __expf(m0 - mn0), a1 = __expf(m1 - mn1);

        float s0 = 0.f, s1 = 0.f;
#pragma unroll
        for (int nt = 0; nt < 4; nt++) {
            float p0 = __expf(S[nt][0] - mn0);
            float p1 = __expf(S[nt][1] - mn0);
            float p2 = __expf(S[nt][2] - mn1);
            float p3 = __expf(S[nt][3] - mn1);
            s0 += p0 + p1;
            s1 += p2 + p3;
            __half h0, l0_, h1, l1_, h2, l2_, h3, l3_;
            split_h(p0, h0, l0_); split_h(p1, h1, l1_);
            split_h(p2, h2, l2_); split_h(p3, h3, l3_);
            const int col = wn * 32 + nt * 8 + 2 * t;
            const int r0 = wm * 16 + g, r1 = r0 + 8;
            *(__half2*)&smh[OPH2 + r0 * SCF + col] = __half2(h0, h1);
            *(__half2*)&smh[OPL2 + r0 * SCF + col] = __half2(l0_, l1_);
            *(__half2*)&smh[OPH2 + r1 * SCF + col] = __half2(h2, h3);
            *(__half2*)&smh[OPL2 + r1 * SCF + col] = __half2(l2_, l3_);
        }
        s0 += __shfl_xor_sync(0xffffffffu, s0, 1);
        s0 += __shfl_xor_sync(0xffffffffu, s0, 2);
        s1 += __shfl_xor_sync(0xffffffffu, s1, 1);
        s1 += __shfl_xor_sync(0xffffffffu, s1, 2);
        if (t == 0) {
            ps[wn * 64 + wm * 16 + g]     = s0;
            ps[wn * 64 + wm * 16 + 8 + g] = s1;
        }
        __syncthreads();
        l0 = l0 * a0 + ps[wm * 16 + g]     + ps[64 + wm * 16 + g];
        l1 = l1 * a1 + ps[wm * 16 + 8 + g] + ps[64 + wm * 16 + 8 + g];
        m0 = mn0; m1 = mn1;
#pragma unroll
        for (int dc = 0; dc < 4; dc++)
#pragma unroll
            for (int nt = 0; nt < 4; nt++) {
                O[dc][nt][0] *= a0; O[dc][nt][1] *= a0;
                O[dc][nt][2] *= a1; O[dc][nt][3] *= a1;
            }

        // ---- O += P @ V, pipelined over 4 d-chunks ----
        issue_kv(g_Vh16, g_Vl16, k0, 0, 0);
        for (int dc = 0; dc < 4; dc++) {
            const int buf = dc & 1;
            if (dc < 3) {
                issue_kv(g_Vh16, g_Vl16, k0, dc + 1, buf ^ 1);
                asm volatile("cp.async.wait_group 1;" ::: "memory");
            } else {
                asm volatile("cp.async.wait_group 0;" ::: "memory");
            }
            __syncthreads();

            const int okh = OCH + buf * 2 * CHUNK_E;
            const int okl = okh + CHUNK_E;
#pragma unroll
            for (int kk = 0; kk < 4; kk++) {
                uint32_t ph[4], pl[4], vh[2][4], vl[2][4];
                ldsm4(ph, sb + (uint32_t)(OPH2 + (wm * 16) * SCF + kk * 16 + aoffP) * 2);
                ldsm4(pl, sb + (uint32_t)(OPL2 + (wm * 16) * SCF + kk * 16 + aoffP) * 2);
#pragma unroll
                for (int pr = 0; pr < 2; pr++) {
                    const int vb = (kk * 16) * SCF + wn * 32 + pr * 16;
                    ldsm4t(vh[pr], sb + (uint32_t)(okh + vb + voffV) * 2);
                    ldsm4t(vl[pr], sb + (uint32_t)(okl + vb + voffV) * 2);
                }
#pragma unroll
                for (int nt = 0; nt < 4; nt++) {
                    const int pr = nt >> 1, hf = (nt & 1) * 2;
                    uint32_t bH[2] = { vh[pr][hf], vh[pr][hf + 1] };
                    uint32_t bL[2] = { vl[pr][hf], vl[pr][hf + 1] };
                    mma16h(O[dc][nt], ph, bH);
                    mma16h(O[dc][nt], ph, bL);
                    mma16h(O[dc][nt], pl, bH);
                }
            }
            __syncthreads();
        }
    }

    // ---- epilogue ----
    const float i0 = 1.0f / l0, i1 = 1.0f / l1;
#pragma unroll
    for (int dc = 0; dc < 4; dc++)
#pragma unroll
        for (int nt = 0; nt < 4; nt++) {
            const int col = h * HD + dc * 64 + wn * 32 + nt * 8 + 2 * t;
            const size_t r0 = (size_t)(t0 + wm * 16 + g) * QD + col;
            const size_t r1 = (size_t)(t0 + wm * 16 + 8 + g) * QD + col;
            *(float2*)&g_A[r0] = make_float2(O[dc][nt][0] * i0, O[dc][nt][1] * i0);
            *(float2*)&g_A[r1] = make_float2(O[dc][nt][2] * i1, O[dc][nt][3] * i1);
        }
}

// ---------------------------------------------------------------------------
// launch
// ---------------------------------------------------------------------------
extern "C" void kernel_launch(void* const* d_in, const int* in_sizes, int n_in,
                              void* d_out, int out_size)
{
    (void)in_sizes; (void)n_in; (void)out_size;
    const float* hs   = (const float*)d_in[0];
    const float* cosp = (const float*)d_in[1];
    const float* sinp = (const float*)d_in[2];
    const float* Wq   = (const float*)d_in[3];
    const float* Wk   = (const float*)d_in[4];
    const float* Wv   = (const float*)d_in[5];
    const float* Wo   = (const float*)d_in[6];
    const float* qw   = (const float*)d_in[7];
    const float* kw   = (const float*)d_in[8];
    float* out = (float*)d_out;

    float *pQKV, *pA;
    __half *phs, *pWqkv, *pWo, *pA16;
    __half *pQh, *pQl, *pKh, *pKl, *pVh, *pVl;
    cudaGetSymbolAddress((void**)&pQKV, g_QKV);
    cudaGetSymbolAddress((void**)&pA,   g_A);
    cudaGetSymbolAddress((void**)&phs,  g_hs16);
    cudaGetSymbolAddress((void**)&pWqkv, g_Wqkv16);
    cudaGetSymbolAddress((void**)&pWo,  g_Wo16);
    cudaGetSymbolAddress((void**)&pA16, g_A16);
    cudaGetSymbolAddress((void**)&pQh,  g_Qh16);
    cudaGetSymbolAddress((void**)&pQl,  g_Ql16);
    cudaGetSymbolAddress((void**)&pKh,  g_Kh16);
    cudaGetSymbolAddress((void**)&pKl,  g_Kl16);
    cudaGetSymbolAddress((void**)&pVh,  g_Vh16);
    cudaGetSymbolAddress((void**)&pVl,  g_Vl16);

    // 0. operand prep
    {
        int n = L * HID / 4;
        conv_h_kernel<<<(n + 255) / 256, 256>>>(hs, phs, n);
    }
    transpose_h_kernel<<<dim3(QD / 32, HID / 32), dim3(32, 8)>>>(Wq, pWqkv, HID, QD);
    transpose_h_kernel<<<dim3(KD / 32, HID / 32), dim3(32, 8)>>>(Wk, pWqkv + (size_t)QD * HID, HID, KD);
    transpose_h_kernel<<<dim3(KD / 32, HID / 32), dim3(32, 8)>>>(Wv, pWqkv + (size_t)(QD + KD) * HID, HID, KD);
    transpose_h_kernel<<<dim3(HID / 32, QD / 32), dim3(32, 8)>>>(Wo, pWo, QD, HID);

    cudaFuncSetAttribute(hgemm, cudaFuncAttributeMaxDynamicSharedMemorySize, HGSM);

    // 1. fused QKV projection (N = 4096)
    hgemm<<<dim3(QKVD / 128, L / 128), 256, HGSM>>>(phs, pWqkv, pQKV, QKVD, HID);

    // 2. RMSNorm + RoPE -> fp16 hi/lo (strided reads from fused buffer); V split
    norm_rope_split_kernel<<<dim3(L, NH), 256>>>(pQKV, QKVD, qw, cosp, sinp, pQh, pQl, QD);
    norm_rope_split_kernel<<<dim3(L, NKV), 256>>>(pQKV + QD, QKVD, kw, cosp, sinp, pKh, pKl, KD);
    {
        int n = L * KD / 4;
        split_h_strided_kernel<<<(n + 255) / 256, 256>>>(pQKV + QD + KD, pVh, pVl, n);
    }

    // 3. attention
    cudaFuncSetAttribute(attn_h_kernel,
                         cudaFuncAttributeMaxDynamicSharedMemorySize, ATTH_SMEM);
    attn_h_kernel<<<dim3(SEQ / 64, L / SEQ, NH), 256, ATTH_SMEM>>>();

    // 3b. A -> fp16
    {
        int n = L * QD / 4;
        conv_h_kernel<<<(n + 255) / 256, 256>>>(pA, pA16, n);
    }

    // 4. output projection
    hgemm<<<dim3(HID / 128, L / 128), 256, HGSM>>>(pA16, pWo, out, HID, QD);
}

// round 8
// speedup vs baseline: 2.8184x; 1.1648x over previous
#include <cuda_runtime.h>
#include <cuda_fp16.h>
#include <math.h>
#include <stdint.h>

// ---------------------------------------------------------------------------
// Problem constants
// ---------------------------------------------------------------------------
#define L     4096
#define HID   2560
#define NH    8
#define NKV   4
#define HD    256
#define QD    (NH*HD)    // 2048
#define KD    (NKV*HD)   // 1024
#define QKVD  (QD + 2*KD) // 4096
#define SCALING 0.0625f
#define SEQ   1024

// ---------------------------------------------------------------------------
// Scratch
// ---------------------------------------------------------------------------
__device__ float g_QKV[L * QKVD];
__device__ __half g_hs16[L * HID];
__device__ __half g_Wqkv16[QKVD * HID];  // [N][K] transposed, Q|K|V rows
__device__ __half g_Wo16[HID * QD];
__device__ __half g_A16[L * QD];         // attention out, fp16 (direct)
__device__ __half g_Qh16[L * QD], g_Ql16[L * QD];
__device__ __half g_Kh16[L * KD], g_Kl16[L * KD];
__device__ __half g_Vh16[L * KD], g_Vl16[L * KD];

// ---------------------------------------------------------------------------
// helpers
// ---------------------------------------------------------------------------
__device__ __forceinline__ void mma16h(float* c, const uint32_t* a, const uint32_t* b) {
    asm volatile(
        "mma.sync.aligned.m16n8k16.row.col.f32.f16.f16.f32 "
        "{%0,%1,%2,%3}, {%4,%5,%6,%7}, {%8,%9}, {%0,%1,%2,%3};"
        : "+f"(c[0]), "+f"(c[1]), "+f"(c[2]), "+f"(c[3])
        : "r"(a[0]), "r"(a[1]), "r"(a[2]), "r"(a[3]), "r"(b[0]), "r"(b[1]));
}
__device__ __forceinline__ void ldsm4(uint32_t* r, uint32_t addr) {
    asm volatile("ldmatrix.sync.aligned.m8n8.x4.shared.b16 {%0,%1,%2,%3}, [%4];"
                 : "=r"(r[0]), "=r"(r[1]), "=r"(r[2]), "=r"(r[3]) : "r"(addr));
}
__device__ __forceinline__ void ldsm4t(uint32_t* r, uint32_t addr) {
    asm volatile("ldmatrix.sync.aligned.m8n8.x4.trans.shared.b16 {%0,%1,%2,%3}, [%4];"
                 : "=r"(r[0]), "=r"(r[1]), "=r"(r[2]), "=r"(r[3]) : "r"(addr));
}
__device__ __forceinline__ void cpasync16(uint32_t s, const void* g) {
    asm volatile("cp.async.cg.shared.global [%0], [%1], 16;" :: "r"(s), "l"(g));
}
__device__ __forceinline__ void split_h(float x, __half& h, __half& l) {
    h = __float2half_rn(x);
    l = __float2half_rn(x - __half2float(h));
}

// ---------------------------------------------------------------------------
// prep kernels
// ---------------------------------------------------------------------------
__global__ void conv_h_kernel(const float* __restrict__ in,
                              __half* __restrict__ out, int n4)
{
    int i = blockIdx.x * blockDim.x + threadIdx.x;
    if (i >= n4) return;
    float4 v = ((const float4*)in)[i];
    ((__half2*)out)[2 * i]     = __half2(__float2half_rn(v.x), __float2half_rn(v.y));
    ((__half2*)out)[2 * i + 1] = __half2(__float2half_rn(v.z), __float2half_rn(v.w));
}

// fused transpose of Wq|Wk|Wv (all K=HID) into g_Wqkv16 [N][K]
__global__ void transpose_qkv_kernel(const float* __restrict__ Wq,
                                     const float* __restrict__ Wk,
                                     const float* __restrict__ Wv,
                                     __half* __restrict__ T)
{
    __shared__ float t[32][33];
    const int z = blockIdx.z;
    const int Ndim = (z == 0) ? QD : KD;
    const int n0 = blockIdx.x * 32;
    if (n0 >= Ndim) return;
    const int k0 = blockIdx.y * 32;
    const float* W = (z == 0) ? Wq : (z == 1 ? Wk : Wv);
    __half* To = T + (size_t)((z == 0) ? 0 : (z == 1 ? QD : QD + KD)) * HID;
    const int tx = threadIdx.x, ty = threadIdx.y;
#pragma unroll
    for (int j = 0; j < 4; j++)
        t[ty + j * 8][tx] = W[(size_t)(k0 + ty + j * 8) * Ndim + n0 + tx];
    __syncthreads();
#pragma unroll
    for (int j = 0; j < 4; j++)
        To[(size_t)(n0 + ty + j * 8) * HID + k0 + tx] = __float2half_rn(t[tx][ty + j * 8]);
}

__global__ void transpose_h_kernel(const float* __restrict__ W,
                                   __half* __restrict__ T, int Kdim, int Ndim)
{
    __shared__ float t[32][33];
    const int k0 = blockIdx.y * 32, n0 = blockIdx.x * 32;
    const int tx = threadIdx.x, ty = threadIdx.y;
#pragma unroll
    for (int j = 0; j < 4; j++)
        t[ty + j * 8][tx] = W[(size_t)(k0 + ty + j * 8) * Ndim + n0 + tx];
    __syncthreads();
#pragma unroll
    for (int j = 0; j < 4; j++)
        T[(size_t)(n0 + ty + j * 8) * Kdim + k0 + tx] = __float2half_rn(t[tx][ty + j * 8]);
}

// ---------------------------------------------------------------------------
// single-fp16 GEMM, K-chunk 64, 2 CTAs/SM: C[M,Ntot](f32) = A @ B^T
// ---------------------------------------------------------------------------
#define SAB 72
#define TILE_E (128*SAB)           // 9216
#define STG_E (2*TILE_E)
#define HGSM (2*STG_E*2)           // 73728 bytes

__global__ __launch_bounds__(256, 2)
void hgemm(const __half* __restrict__ Ap, const __half* __restrict__ Bp,
           float* __restrict__ C, int Ntot, int K)
{
    extern __shared__ __half sh16[];
    const int tid  = threadIdx.x;
    const int lane = tid & 31, wid = tid >> 5;
    const int wm = wid >> 2, wn = wid & 3;
    const int g = lane >> 2, t = lane & 3;
    const int m0 = blockIdx.y * 128, n0 = blockIdx.x * 128;

    const uint32_t sbase = (uint32_t)__cvta_generic_to_shared(sh16);
    const __half* baseA = Ap + (size_t)m0 * K;
    const __half* baseB = Bp + (size_t)n0 * K;

    float acc[4][4][4];
#pragma unroll
    for (int mt = 0; mt < 4; mt++)
#pragma unroll
        for (int nt = 0; nt < 4; nt++)
#pragma unroll
            for (int r = 0; r < 4; r++) acc[mt][nt][r] = 0.f;

    const int a_off = ((lane & 7) + ((lane >> 3) & 1) * 8) * SAB + ((lane >> 4) & 1) * 8;
    const int b_off = ((lane & 7) + ((lane >> 4) & 1) * 8) * SAB + ((lane >> 3) & 1) * 8;

    auto issue_copy = [&](int c, int buf) {
        const int koff = c * 64;
#pragma unroll
        for (int i = 0; i < 8; i++) {
            const int f = tid + i * 256;
            const int tile = f >> 10;
            const int slot = f & 1023;
            const int row = slot >> 3, seg = slot & 7;
            const __half* gp = (tile ? baseB : baseA) + (size_t)row * K + koff + seg * 8;
            const uint32_t dst = sbase +
                (uint32_t)(buf * STG_E + tile * TILE_E + row * SAB + seg * 8) * 2;
            cpasync16(dst, gp);
        }
        asm volatile("cp.async.commit_group;" ::: "memory");
    };

    const int nkb = K >> 6;
    issue_copy(0, 0);

    for (int kb = 0; kb < nkb; kb++) {
        const int cur = kb & 1;
        if (kb + 1 < nkb) {
            issue_copy(kb + 1, cur ^ 1);
            asm volatile("cp.async.wait_group 1;" ::: "memory");
        } else {
            asm volatile("cp.async.wait_group 0;" ::: "memory");
        }
        __syncthreads();

        const uint32_t sA = sbase + (uint32_t)(cur * STG_E) * 2;
        const uint32_t sB = sA + (uint32_t)TILE_E * 2;

#pragma unroll
        for (int ks = 0; ks < 4; ks++) {
            const int kbase = ks * 16;
            uint32_t af[4][4], bf[2][4];
#pragma unroll
            for (int mt = 0; mt < 4; mt++)
                ldsm4(af[mt], sA + (uint32_t)((wm * 64 + mt * 16) * SAB + kbase + a_off) * 2);
#pragma unroll
            for (int np = 0; np < 2; np++)
                ldsm4(bf[np], sB + (uint32_t)((wn * 32 + np * 16) * SAB + kbase + b_off) * 2);
#pragma unroll
            for (int mt = 0; mt < 4; mt++)
#pragma unroll
                for (int nt = 0; nt < 4; nt++) {
                    const int pr = nt >> 1, hf = (nt & 1) * 2;
                    uint32_t bb[2] = { bf[pr][hf], bf[pr][hf + 1] };
                    mma16h(acc[mt][nt], af[mt], bb);
                }
        }
        __syncthreads();
    }

#pragma unroll
    for (int mt = 0; mt < 4; mt++) {
        const int r0 = m0 + wm * 64 + mt * 16 + g;
#pragma unroll
        for (int nt = 0; nt < 4; nt++) {
            const int c0 = n0 + wn * 32 + nt * 8 + t * 2;
            *(float2*)&C[(size_t)r0 * Ntot + c0] =
                make_float2(acc[mt][nt][0], acc[mt][nt][1]);
            *(float2*)&C[(size_t)(r0 + 8) * Ntot + c0] =
                make_float2(acc[mt][nt][2], acc[mt][nt][3]);
        }
    }
}

// ---------------------------------------------------------------------------
// Unified norm/rope/split: grid (L, 16).
//  h<8: Q rmsnorm+rope; 8<=h<12: K rmsnorm+rope; h>=12: V split only.
// ---------------------------------------------------------------------------
__global__ __launch_bounds__(256)
void prep_qkv_kernel(const float* __restrict__ QKV,
                     const float* __restrict__ qw,
                     const float* __restrict__ kw,
                     const float* __restrict__ cosp,
                     const float* __restrict__ sinp,
                     __half* __restrict__ Qh, __half* __restrict__ Ql,
                     __half* __restrict__ Kh, __half* __restrict__ Kl,
                     __half* __restrict__ Vh, __half* __restrict__ Vl)
{
    const int t = blockIdx.x;
    const int h = blockIdx.y;
    const int d = threadIdx.x;

    if (h >= 12) {
        const int hv = h - 12;
        float x = QKV[(size_t)t * QKVD + QD + KD + hv * HD + d];
        __half hi, lo;
        split_h(x, hi, lo);
        const size_t oo = (size_t)t * KD + hv * HD + d;
        Vh[oo] = hi;
        Vl[oo] = lo;
        return;
    }

    const bool isQ = (h < 8);
    const int hh = isQ ? h : h - 8;
    const float* w = isQ ? qw : kw;
    float x = QKV[(size_t)t * QKVD + (isQ ? 0 : QD) + hh * HD + d];

    float v = x * x;
#pragma unroll
    for (int o = 16; o; o >>= 1) v += __shfl_xor_sync(0xffffffffu, v, o);

    __shared__ float ws[8];
    __shared__ float buf[HD];
    if ((d & 31) == 0) ws[d >> 5] = v;
    __syncthreads();
    float ss = ws[0] + ws[1] + ws[2] + ws[3] + ws[4] + ws[5] + ws[6] + ws[7];

    float r = rsqrtf(ss * (1.0f / HD) + 1e-6f);
    float xn = x * r * (1.0f + w[d]);
    buf[d] = xn;
    __syncthreads();

    float rot = (d < HD / 2) ? -buf[d + HD / 2] : buf[d - HD / 2];
    float c = cosp[(size_t)t * HD + d];
    float s = sinp[(size_t)t * HD + d];
    float xr = xn * c + rot * s;

    __half hi, lo;
    split_h(xr, hi, lo);
    const size_t oo = (size_t)t * (isQ ? QD : KD) + hh * HD + d;
    if (isQ) { Qh[oo] = hi; Ql[oo] = lo; }
    else     { Kh[oo] = hi; Kl[oo] = lo; }
}

// ---------------------------------------------------------------------------
// Flash attention, fp16 hi/lo split, cross-phase prefetched pipeline.
// ---------------------------------------------------------------------------
#define SQF 264
#define SCF 72
#define CHUNK_E (64*SCF)
#define OQH2 0
#define OQL2 (64*SQF)
#define OCH  (2*64*SQF)
#define OPH2 (OCH + 4*CHUNK_E)
#define OPL2 (OPH2 + CHUNK_E)
#define OEND2 (OPL2 + CHUNK_E)
#define ATTH_SMEM (OEND2*2 + 256*4)

__global__ __launch_bounds__(256, 1)
void attn_h_kernel()
{
    extern __shared__ __half smh[];
    float* pm = (float*)(smh + OEND2);
    float* ps = pm + 128;

    const int qt  = (int)gridDim.x - 1 - (int)blockIdx.x;  // long diagonals first
    const int seq = blockIdx.y;
    const int h   = blockIdx.z;
    const int kvh = h >> 1;

    const int tid  = threadIdx.x;
    const int lane = tid & 31, wid = tid >> 5;
    const int wm = wid >> 1, wn = wid & 1;
    const int g = lane >> 2, t = lane & 3;

    const int t0 = seq * SEQ + qt * 64;
    const uint32_t sb = (uint32_t)__cvta_generic_to_shared(smh);

    const int aoffQ = ((lane & 7) + ((lane >> 3) & 1) * 8) * SQF + ((lane >> 4) & 1) * 8;
    const int aoffP = ((lane & 7) + ((lane >> 3) & 1) * 8) * SCF + ((lane >> 4) & 1) * 8;
    const int boffK = ((lane & 7) + ((lane >> 4) & 1) * 8) * SCF + ((lane >> 3) & 1) * 8;
    const int voffV = aoffP;

    auto issue_kv = [&](const __half* gh, const __half* gl, int k0, int dc, int buf) {
#pragma unroll
        for (int i = 0; i < 4; i++) {
            int f = tid + i * 256;
            int tile = f >> 9;
            int slot = f & 511;
            int row = slot >> 3, seg = slot & 7;
            const __half* gp = (tile ? gl : gh) +
                (size_t)(k0 + row) * KD + kvh * HD + dc * 64 + seg * 8;
            cpasync16(sb + (uint32_t)(OCH + (buf * 2 + tile) * CHUNK_E + row * SCF + seg * 8) * 2, gp);
        }
        asm volatile("cp.async.commit_group;" ::: "memory");
    };

    // prefetch K chunk0 of kt=0, then resident Q hi/lo
    issue_kv(g_Kh16, g_Kl16, seq * SEQ, 0, 0);
    {
        const __half* gqh = g_Qh16 + (size_t)t0 * QD + h * HD;
        const __half* gql = g_Ql16 + (size_t)t0 * QD + h * HD;
#pragma unroll
        for (int i = 0; i < 16; i++) {
            int f = tid + i * 256;
            int tile = f >> 11;
            int slot = f & 2047;
            int row = slot >> 5, seg = slot & 31;
            const __half* gp = (tile ? gql : gqh) + (size_t)row * QD + seg * 8;
            cpasync16(sb + (uint32_t)((tile ? OQL2 : OQH2) + row * SQF + seg * 8) * 2, gp);
        }
        asm volatile("cp.async.commit_group;" ::: "memory");
        asm volatile("cp.async.wait_group 1;" ::: "memory");  // Q group done (FIFO: K0 first? no: wait<=1 pending => K0 done)
        asm volatile("cp.async.wait_group 0;" ::: "memory");  // both done before first use
    }
    __syncthreads();

    float O[4][4][4];
#pragma unroll
    for (int dc = 0; dc < 4; dc++)
#pragma unroll
        for (int nt = 0; nt < 4; nt++)
#pragma unroll
            for (int r = 0; r < 4; r++) O[dc][nt][r] = 0.f;
    float m0 = -INFINITY, m1 = -INFINITY, l0 = 0.f, l1 = 0.f;

    for (int kt = 0; kt <= qt; kt++) {
        const int k0 = seq * SEQ + kt * 64;

        float S[4][4];
#pragma unroll
        for (int nt = 0; nt < 4; nt++)
#pragma unroll
            for (int r = 0; r < 4; r++) S[nt][r] = 0.f;

        // ---- S = Q @ K^T, pipelined (chunk0 already in flight/resident) ----
        for (int dc = 0; dc < 4; dc++) {
            const int buf = dc & 1;
            if (dc < 3) {
                issue_kv(g_Kh16, g_Kl16, k0, dc + 1, buf ^ 1);
                asm volatile("cp.async.wait_group 1;" ::: "memory");
            } else {
                asm volatile("cp.async.wait_group 0;" ::: "memory");
            }
            __syncthreads();

            const int okh = OCH + buf * 2 * CHUNK_E;
            const int okl = okh + CHUNK_E;
#pragma unroll
            for (int ks = 0; ks < 4; ks++) {
                const int kq = dc * 64 + ks * 16;
                uint32_t qh[4], ql[4], kh[2][4], kl[2][4];
                ldsm4(qh, sb + (uint32_t)(OQH2 + (wm * 16) * SQF + kq + aoffQ) * 2);
                ldsm4(ql, sb + (uint32_t)(OQL2 + (wm * 16) * SQF + kq + aoffQ) * 2);
#pragma unroll
                for (int pr = 0; pr < 2; pr++) {
                    const int nb = (wn * 32 + pr * 16) * SCF + ks * 16;
                    ldsm4(kh[pr], sb + (uint32_t)(okh + nb + boffK) * 2);
                    ldsm4(kl[pr], sb + (uint32_t)(okl + nb + boffK) * 2);
                }
#pragma unroll
                for (int nt = 0; nt < 4; nt++) {
                    const int pr = nt >> 1, hf = (nt & 1) * 2;
                    uint32_t bH[2] = { kh[pr][hf], kh[pr][hf + 1] };
                    uint32_t bL[2] = { kl[pr][hf], kl[pr][hf + 1] };
                    mma16h(S[nt], qh, bH);
                    mma16h(S[nt], qh, bL);
                    mma16h(S[nt], ql, bH);
                }
            }
            __syncthreads();
        }

        // V chunk0 prefetch overlaps softmax
        issue_kv(g_Vh16, g_Vl16, k0, 0, 0);

        // ---- scale + causal mask ----
#pragma unroll
        for (int nt = 0; nt < 4; nt++) {
#pragma unroll
            for (int r = 0; r < 4; r++) S[nt][r] *= SCALING;
            if (kt == qt) {
                const int cl = wn * 32 + nt * 8 + 2 * t;
                const int rl0 = wm * 16 + g, rl1 = rl0 + 8;
                if (cl     > rl0) S[nt][0] = -INFINITY;
                if (cl + 1 > rl0) S[nt][1] = -INFINITY;
                if (cl     > rl1) S[nt][2] = -INFINITY;
                if (cl + 1 > rl1) S[nt][3] = -INFINITY;
            }
        }

        // ---- online softmax ----
        float rm0 = -INFINITY, rm1 = -INFINITY;
#pragma unroll
        for (int nt = 0; nt < 4; nt++) {
            rm0 = fmaxf(rm0, fmaxf(S[nt][0], S[nt][1]));
            rm1 = fmaxf(rm1, fmaxf(S[nt][2], S[nt][3]));
        }
        rm0 = fmaxf(rm0, __shfl_xor_sync(0xffffffffu, rm0, 1));
        rm0 = fmaxf(rm0, __shfl_xor_sync(0xffffffffu, rm0, 2));
        rm1 = fmaxf(rm1, __shfl_xor_sync(0xffffffffu, rm1, 1));
        rm1 = fmaxf(rm1, __shfl_xor_sync(0xffffffffu, rm1, 2));
        if (t == 0) {
            pm[wn * 64 + wm * 16 + g]     = rm0;
            pm[wn * 64 + wm * 16 + 8 + g] = rm1;
        }
        __syncthreads();
        rm0 = fmaxf(rm0, pm[(wn ^ 1) * 64 + wm * 16 + g]);
        rm1 = fmaxf(rm1, pm[(wn ^ 1) * 64 + wm * 16 + 8 + g]);

        const float mn0 = fmaxf(m0, rm0), mn1 = fmaxf(m1, rm1);
        const float a0 = __expf(m0 - mn0), a1 = __expf(m1 - mn1);

        float s0 = 0.f, s1 = 0.f;
#pragma unroll
        for (int nt = 0; nt < 4; nt++) {
            float p0 = __expf(S[nt][0] - mn0);
            float p1 = __expf(S[nt][1] - mn0);
            float p2 = __expf(S[nt][2] - mn1);
            float p3 = __expf(S[nt][3] - mn1);
            s0 += p0 + p1;
            s1 += p2 + p3;
            __half h0, l0_, h1, l1_, h2, l2_, h3, l3_;
            split_h(p0, h0, l0_); split_h(p1, h1, l1_);
            split_h(p2, h2, l2_); split_h(p3, h3, l3_);
            const int col = wn * 32 + nt * 8 + 2 * t;
            const int r0 = wm * 16 + g, r1 = r0 + 8;
            *(__half2*)&smh[OPH2 + r0 * SCF + col] = __half2(h0, h1);
            *(__half2*)&smh[OPL2 + r0 * SCF + col] = __half2(l0_, l1_);
            *(__half2*)&smh[OPH2 + r1 * SCF + col] = __half2(h2, h3);
            *(__half2*)&smh[OPL2 + r1 * SCF + col] = __half2(l2_, l3_);
        }
        s0 += __shfl_xor_sync(0xffffffffu, s0, 1);
        s0 += __shfl_xor_sync(0xffffffffu, s0, 2);
        s1 += __shfl_xor_sync(0xffffffffu, s1, 1);
        s1 += __shfl_xor_sync(0xffffffffu, s1, 2);
        if (t == 0) {
            ps[wn * 64 + wm * 16 + g]     = s0;
            ps[wn * 64 + wm * 16 + 8 + g] = s1;
        }
        __syncthreads();
        l0 = l0 * a0 + ps[wm * 16 + g]     + ps[64 + wm * 16 + g];
        l1 = l1 * a1 + ps[wm * 16 + 8 + g] + ps[64 + wm * 16 + 8 + g];
        m0 = mn0; m1 = mn1;
#pragma unroll
        for (int dc = 0; dc < 4; dc++)
#pragma unroll
            for (int nt = 0; nt < 4; nt++) {
                O[dc][nt][0] *= a0; O[dc][nt][1] *= a0;
                O[dc][nt][2] *= a1; O[dc][nt][3] *= a1;
            }

        // ---- O += P @ V, pipelined; prefetch next-kt K during last chunk ----
        for (int dc = 0; dc < 4; dc++) {
            const int buf = dc & 1;
            if (dc < 3) {
                issue_kv(g_Vh16, g_Vl16, k0, dc + 1, buf ^ 1);
                asm volatile("cp.async.wait_group 1;" ::: "memory");
            } else {
                asm volatile("cp.async.wait_group 0;" ::: "memory");
                if (kt < qt) issue_kv(g_Kh16, g_Kl16, k0 + 64, 0, 0);
            }
            __syncthreads();

            const int okh = OCH + buf * 2 * CHUNK_E;
            const int okl = okh + CHUNK_E;
#pragma unroll
            for (int kk = 0; kk < 4; kk++) {
                uint32_t ph[4], pl[4], vh[2][4], vl[2][4];
                ldsm4(ph, sb + (uint32_t)(OPH2 + (wm * 16) * SCF + kk * 16 + aoffP) * 2);
                ldsm4(pl, sb + (uint32_t)(OPL2 + (wm * 16) * SCF + kk * 16 + aoffP) * 2);
#pragma unroll
                for (int pr = 0; pr < 2; pr++) {
                    const int vb = (kk * 16) * SCF + wn * 32 + pr * 16;
                    ldsm4t(vh[pr], sb + (uint32_t)(okh + vb + voffV) * 2);
                    ldsm4t(vl[pr], sb + (uint32_t)(okl + vb + voffV) * 2);
                }
#pragma unroll
                for (int nt = 0; nt < 4; nt++) {
                    const int pr = nt >> 1, hf = (nt & 1) * 2;
                    uint32_t bH[2] = { vh[pr][hf], vh[pr][hf + 1] };
                    uint32_t bL[2] = { vl[pr][hf], vl[pr][hf + 1] };
                    mma16h(O[dc][nt], ph, bH);
                    mma16h(O[dc][nt], ph, bL);
                    mma16h(O[dc][nt], pl, bH);
                }
            }
            __syncthreads();
        }
    }

    // ---- epilogue: write fp16 directly ----
    const float i0 = 1.0f / l0, i1 = 1.0f / l1;
#pragma unroll
    for (int dc = 0; dc < 4; dc++)
#pragma unroll
        for (int nt = 0; nt < 4; nt++) {
            const int col = h * HD + dc * 64 + wn * 32 + nt * 8 + 2 * t;
            const size_t r0 = (size_t)(t0 + wm * 16 + g) * QD + col;
            const size_t r1 = (size_t)(t0 + wm * 16 + 8 + g) * QD + col;
            *(__half2*)&g_A16[r0] =
                __floats2half2_rn(O[dc][nt][0] * i0, O[dc][nt][1] * i0);
            *(__half2*)&g_A16[r1] =
                __floats2half2_rn(O[dc][nt][2] * i1, O[dc][nt][3] * i1);
        }
}

// ---------------------------------------------------------------------------
// launch
// ---------------------------------------------------------------------------
extern "C" void kernel_launch(void* const* d_in, const int* in_sizes, int n_in,
                              void* d_out, int out_size)
{
    (void)in_sizes; (void)n_in; (void)out_size;
    const float* hs   = (const float*)d_in[0];
    const float* cosp = (const float*)d_in[1];
    const float* sinp = (const float*)d_in[2];
    const float* Wq   = (const float*)d_in[3];
    const float* Wk   = (const float*)d_in[4];
    const float* Wv   = (const float*)d_in[5];
    const float* Wo   = (const float*)d_in[6];
    const float* qw   = (const float*)d_in[7];
    const float* kw   = (const float*)d_in[8];
    float* out = (float*)d_out;

    float *pQKV;
    __half *phs, *pWqkv, *pWo, *pA16;
    __half *pQh, *pQl, *pKh, *pKl, *pVh, *pVl;
    cudaGetSymbolAddress((void**)&pQKV, g_QKV);
    cudaGetSymbolAddress((void**)&phs,  g_hs16);
    cudaGetSymbolAddress((void**)&pWqkv, g_Wqkv16);
    cudaGetSymbolAddress((void**)&pWo,  g_Wo16);
    cudaGetSymbolAddress((void**)&pA16, g_A16);
    cudaGetSymbolAddress((void**)&pQh,  g_Qh16);
    cudaGetSymbolAddress((void**)&pQl,  g_Ql16);
    cudaGetSymbolAddress((void**)&pKh,  g_Kh16);
    cudaGetSymbolAddress((void**)&pKl,  g_Kl16);
    cudaGetSymbolAddress((void**)&pVh,  g_Vh16);
    cudaGetSymbolAddress((void**)&pVl,  g_Vl16);

    // 0. operand prep
    {
        int n = L * HID / 4;
        conv_h_kernel<<<(n + 255) / 256, 256>>>(hs, phs, n);
    }
    transpose_qkv_kernel<<<dim3(QD / 32, HID / 32, 3), dim3(32, 8)>>>(Wq, Wk, Wv, pWqkv);
    transpose_h_kernel<<<dim3(HID / 32, QD / 32), dim3(32, 8)>>>(Wo, pWo, QD, HID);

    cudaFuncSetAttribute(hgemm, cudaFuncAttributeMaxDynamicSharedMemorySize, HGSM);

    // 1. fused QKV projection (N = 4096)
    hgemm<<<dim3(QKVD / 128, L / 128), 256, HGSM>>>(phs, pWqkv, pQKV, QKVD, HID);

    // 2. unified RMSNorm/RoPE/V-split -> fp16 hi/lo
    prep_qkv_kernel<<<dim3(L, 16), 256>>>(pQKV, qw, kw, cosp, sinp,
                                          pQh, pQl, pKh, pKl, pVh, pVl);

    // 3. attention (epilogue writes fp16 directly)
    cudaFuncSetAttribute(attn_h_kernel,
                         cudaFuncAttributeMaxDynamicSharedMemorySize, ATTH_SMEM);
    attn_h_kernel<<<dim3(SEQ / 64, L / SEQ, NH), 256, ATTH_SMEM>>>();

    // 4. output projection
    hgemm<<<dim3(HID / 128, L / 128), 256, HGSM>>>(pA16, pWo, out, HID, QD);
}